// round 2
// baseline (speedup 1.0000x reference)
#include <cuda_runtime.h>
#include <math.h>

#define NN   100000
#define RR   3
#define EE   320000
#define HIDF 128
#define HH   4
#define DDIM 32
#define HD   128

// ---------------- scratch (device globals; no allocation allowed) ----------
// All arrays accessed via float4 / red.v4 MUST be 16B aligned.
__device__ __align__(16) float g_hs  [RR * NN * HD];   // per-relation projected src feats
__device__ __align__(16) float g_rst [RR * NN * HD];   // aggregation accumulator -> z_r
__device__ __align__(16) float g_el  [RR * NN * HH];
__device__ __align__(16) float g_er  [RR * NN * HH];
__device__ __align__(16) float g_ssum[RR * NN * HH];
__device__ __align__(16) float g_ex  [RR * EE * HH];
__device__ __align__(16) float g_Wcomb[RR * HIDF * HD];
__device__ __align__(16) float g_bcomb[RR * HD];
__device__ __align__(16) float g_Md  [RR * HIDF * HH];
__device__ __align__(16) float g_bd  [RR * HH];
__device__ __align__(16) float g_wsum[RR];
__device__ __align__(16) float g_a   [RR];

// ---------------- helpers --------------------------------------------------
__device__ __forceinline__ void red_add_v4(float* p, float4 v) {
    asm volatile("red.global.add.v4.f32 [%0], {%1,%2,%3,%4};"
                 :: "l"(p), "f"(v.x), "f"(v.y), "f"(v.z), "f"(v.w) : "memory");
}
__device__ __forceinline__ float tanh_fast(float x) {
    float y; asm("tanh.approx.f32 %0, %1;" : "=f"(y) : "f"(x)); return y;
}
__device__ __forceinline__ float eluf(float x) {
    return x > 0.f ? x : expm1f(x);
}

// ---------------- K0: combined weights -------------------------------------
// Wcomb[r] = Wt_src[r] @ Wg[r];  bcomb[r] = bt_src[r] @ Wg[r]
// Md[r]    = Wt_dst @ (Wg[r] . attn_r[r]);  bd[r] = bt_dst @ (Wg[r] . attn_r[r])
__global__ void k_prep(const float* __restrict__ Wt_dst, const float* __restrict__ bt_dst,
                       const float* __restrict__ Wt_src, const float* __restrict__ bt_src,
                       const float* __restrict__ Wg,     const float* __restrict__ attn_r) {
    int r = blockIdx.x / 9;
    int part = blockIdx.x % 9;
    int t = threadIdx.x; // 256
    const float* wg = Wg + r * HIDF * HD;
    if (part < 8) {
        const float* wts = Wt_src + r * HIDF * HIDF;
        #pragma unroll 1
        for (int it = 0; it < 8; it++) {
            int idx = part * 2048 + it * 256 + t;
            int f = idx >> 7, j = idx & 127;
            float s = 0.f;
            for (int g = 0; g < HIDF; g++)
                s += wts[f * HIDF + g] * wg[g * HD + j];
            g_Wcomb[r * HIDF * HD + idx] = s;
        }
    } else {
        __shared__ float ur[HIDF * HH];
        const float* ar = attn_r + r * HH * DDIM;
        for (int i = t; i < HIDF * HH; i += 256) {
            int f = i >> 2, h = i & 3;
            float s = 0.f;
            for (int d = 0; d < DDIM; d++)
                s += wg[f * HD + h * DDIM + d] * ar[h * DDIM + d];
            ur[i] = s;
        }
        __syncthreads();
        for (int i = t; i < HIDF * HH; i += 256) {
            int f = i >> 2, h = i & 3;
            float s = 0.f;
            for (int g = 0; g < HIDF; g++)
                s += Wt_dst[f * HIDF + g] * ur[g * HH + h];
            g_Md[r * HIDF * HH + i] = s;
        }
        if (t < HH) {
            float s = 0.f;
            for (int g = 0; g < HIDF; g++) s += bt_dst[g] * ur[g * HH + t];
            g_bd[r * HH + t] = s;
        }
        if (t < HD) {
            const float* bts = bt_src + r * HIDF;
            float s = 0.f;
            for (int f = 0; f < HIDF; f++) s += bts[f] * wg[f * HD + t];
            g_bcomb[r * HD + t] = s;
        }
    }
}

// ---------------- K1: zero accumulators ------------------------------------
__global__ void k_fill() {
    size_t i = blockIdx.x * (size_t)blockDim.x + threadIdx.x;
    size_t stride = gridDim.x * (size_t)blockDim.x;
    float4 z4 = {0.f, 0.f, 0.f, 0.f};
    size_t n4 = ((size_t)RR * NN * HD) / 4;
    for (size_t k = i; k < n4; k += stride) ((float4*)g_rst)[k] = z4;
    size_t m4 = ((size_t)RR * NN * HH) / 4;
    for (size_t k = i; k < m4; k += stride) ((float4*)g_ssum)[k] = z4;
    if (i < RR) g_wsum[i] = 0.f;
}

// ---------------- K2: hs = src @ Wcomb + bcomb ; el epilogue ----------------
// 256 threads, tile M=64, N=128, K chunked by 32.
__global__ __launch_bounds__(256) void k_gemm_hs(const float* __restrict__ src_feats,
                                                 const float* __restrict__ attn_l) {
    __shared__ float As[64 * 36];    // [row][k-chunk], pad 36
    __shared__ float Ws[32 * 128];   // [k][col]
    const int r = blockIdx.y;
    const int row0 = blockIdx.x * 64;
    const int t = threadIdx.x;
    const int tx = t & 15, ty = t >> 4;
    const float* A = src_feats + (size_t)r * NN * HIDF;
    const float* W = g_Wcomb + r * HIDF * HD;

    float acc[4][8];
    #pragma unroll
    for (int i = 0; i < 4; i++)
        #pragma unroll
        for (int j = 0; j < 8; j++) acc[i][j] = 0.f;

    const int rr = t >> 2, kk = (t & 3) * 8;
    const int grow = row0 + rr;

    for (int k0 = 0; k0 < HIDF; k0 += 32) {
        float4 a0 = {0,0,0,0}, a1 = {0,0,0,0};
        if (grow < NN) {
            const float* ap = &A[(size_t)grow * HIDF + k0 + kk];
            a0 = *(const float4*)ap;
            a1 = *(const float4*)(ap + 4);
        }
        *(float4*)&As[rr * 36 + kk]     = a0;
        *(float4*)&As[rr * 36 + kk + 4] = a1;
        {
            int wr = t >> 3, wc = (t & 7) * 16;
            #pragma unroll
            for (int q = 0; q < 4; q++)
                *(float4*)&Ws[wr * 128 + wc + q * 4] =
                    *(const float4*)&W[(k0 + wr) * HD + wc + q * 4];
        }
        __syncthreads();
        #pragma unroll
        for (int k = 0; k < 32; k++) {
            float av[4];
            #pragma unroll
            for (int i = 0; i < 4; i++) av[i] = As[(ty * 4 + i) * 36 + k];
            float wv[8];
            *(float4*)&wv[0] = *(const float4*)&Ws[k * 128 + tx * 4];
            *(float4*)&wv[4] = *(const float4*)&Ws[k * 128 + 64 + tx * 4];
            #pragma unroll
            for (int i = 0; i < 4; i++)
                #pragma unroll
                for (int j = 0; j < 8; j++) acc[i][j] += av[i] * wv[j];
        }
        __syncthreads();
    }

    // epilogue: add bcomb, store hs, compute el via 8-lane reduction
    float alv[8], bcv[8];
    #pragma unroll
    for (int j = 0; j < 4; j++) {
        int cA = tx * 4 + j, cB = 64 + tx * 4 + j;
        alv[j]     = attn_l[r * HD + cA];  bcv[j]     = g_bcomb[r * HD + cA];
        alv[4 + j] = attn_l[r * HD + cB];  bcv[4 + j] = g_bcomb[r * HD + cB];
    }
    const int h1 = tx >> 3;
    #pragma unroll
    for (int i = 0; i < 4; i++) {
        int n = row0 + ty * 4 + i;
        float v[8];
        #pragma unroll
        for (int j = 0; j < 8; j++) v[j] = acc[i][j] + bcv[j];
        float p1 = v[0]*alv[0] + v[1]*alv[1] + v[2]*alv[2] + v[3]*alv[3];
        float p2 = v[4]*alv[4] + v[5]*alv[5] + v[6]*alv[6] + v[7]*alv[7];
        p1 += __shfl_xor_sync(0xffffffffu, p1, 1);
        p1 += __shfl_xor_sync(0xffffffffu, p1, 2);
        p1 += __shfl_xor_sync(0xffffffffu, p1, 4);
        p2 += __shfl_xor_sync(0xffffffffu, p2, 1);
        p2 += __shfl_xor_sync(0xffffffffu, p2, 2);
        p2 += __shfl_xor_sync(0xffffffffu, p2, 4);
        if (n < NN) {
            float* hp = &g_hs[((size_t)r * NN + n) * HD];
            float4 s0 = {v[0], v[1], v[2], v[3]};
            float4 s1 = {v[4], v[5], v[6], v[7]};
            *(float4*)(hp + tx * 4)      = s0;
            *(float4*)(hp + 64 + tx * 4) = s1;
            if ((tx & 7) == 0) {
                g_el[((size_t)r * NN + n) * HH + h1]     = p1;
                g_el[((size_t)r * NN + n) * HH + 2 + h1] = p2;
            }
        }
    }
}

// ---------------- K3: er = dst_feat @ Md + bd (all relations, warp/node) ----
__global__ void k_er(const float* __restrict__ dst_feat) {
    int warp = (blockIdx.x * blockDim.x + threadIdx.x) >> 5;
    int lane = threadIdx.x & 31;
    if (warp >= NN) return;
    float4 f = *(const float4*)&dst_feat[(size_t)warp * HIDF + lane * 4];
    float acc[RR * HH];
    #pragma unroll
    for (int rh = 0; rh < RR * HH; rh++) {
        int r = rh >> 2, h = rh & 3;
        const float* md = &g_Md[r * HIDF * HH + (lane * 4) * HH + h];
        acc[rh] = f.x * md[0] + f.y * md[HH] + f.z * md[2 * HH] + f.w * md[3 * HH];
    }
    #pragma unroll
    for (int rh = 0; rh < RR * HH; rh++) {
        float v = acc[rh];
        #pragma unroll
        for (int o = 16; o >= 1; o >>= 1) v += __shfl_xor_sync(0xffffffffu, v, o);
        acc[rh] = v;
    }
    if (lane == 0) {
        #pragma unroll
        for (int rh = 0; rh < RR * HH; rh++) {
            int r = rh >> 2, h = rh & 3;
            g_er[((size_t)r * NN + warp) * HH + h] = acc[rh] + g_bd[rh];
        }
    }
}

// ---------------- K4: edge scores: ex = exp(leaky(el[s]+er[d])); ssum +=  ---
__global__ void k_edge1(const int* __restrict__ src_idx, const int* __restrict__ dst_idx) {
    int idx = blockIdx.x * blockDim.x + threadIdx.x;
    if (idx >= RR * EE) return;
    int rel = idx / EE;
    int s = src_idx[idx], d = dst_idx[idx];
    float4 l  = *(const float4*)&g_el[((size_t)rel * NN + s) * HH];
    float4 rv = *(const float4*)&g_er[((size_t)rel * NN + d) * HH];
    float x0 = l.x + rv.x, x1 = l.y + rv.y, x2 = l.z + rv.z, x3 = l.w + rv.w;
    x0 = x0 > 0.f ? x0 : 0.2f * x0;
    x1 = x1 > 0.f ? x1 : 0.2f * x1;
    x2 = x2 > 0.f ? x2 : 0.2f * x2;
    x3 = x3 > 0.f ? x3 : 0.2f * x3;
    float4 ex = {__expf(x0), __expf(x1), __expf(x2), __expf(x3)};
    *(float4*)&g_ex[(size_t)idx * 4] = ex;
    red_add_v4(&g_ssum[((size_t)rel * NN + d) * HH], ex);
}

// ---------------- K5: aggregation: rst[d] += alpha * hs[s] (warp/edge) ------
__global__ void k_edge2(const int* __restrict__ src_idx, const int* __restrict__ dst_idx) {
    int gw = (blockIdx.x * blockDim.x + threadIdx.x) >> 5;
    if (gw >= RR * EE) return;
    int lane = threadIdx.x & 31;
    int rel = gw / EE;
    int s = src_idx[gw], d = dst_idx[gw];
    int h = lane >> 3;
    float exv = g_ex[(size_t)gw * 4 + h];
    float sv  = g_ssum[((size_t)rel * NN + d) * HH + h];
    float alpha = exv / (sv + 1e-9f);
    float4 v = *(const float4*)&g_hs[((size_t)rel * NN + s) * HD + lane * 4];
    v.x *= alpha; v.y *= alpha; v.z *= alpha; v.w *= alpha;
    red_add_v4(&g_rst[((size_t)rel * NN + d) * HD + lane * 4], v);
}

// ---------------- K6: z_r = elu(rst+bias); w = tanh(z@W1+b1)@W2; wsum += ----
__global__ __launch_bounds__(256) void k_gemm_w(const float* __restrict__ bias_g,
                                                const float* __restrict__ W1,
                                                const float* __restrict__ b1,
                                                const float* __restrict__ W2) {
    __shared__ float As[64 * 36];
    __shared__ float Ws[32 * 128];
    const int r = blockIdx.y;
    const int row0 = blockIdx.x * 64;
    const int t = threadIdx.x;
    const int tx = t & 15, ty = t >> 4;
    float* Z = g_rst + (size_t)r * NN * HD;

    float acc[4][8];
    #pragma unroll
    for (int i = 0; i < 4; i++)
        #pragma unroll
        for (int j = 0; j < 8; j++) acc[i][j] = 0.f;

    const int rr = t >> 2, kk = (t & 3) * 8;
    const int grow = row0 + rr;

    for (int k0 = 0; k0 < HD; k0 += 32) {
        float4 a0 = {0,0,0,0}, a1 = {0,0,0,0};
        if (grow < NN) {
            float* zp = &Z[(size_t)grow * HD + k0 + kk];
            a0 = *(float4*)zp;  a1 = *(float4*)(zp + 4);
            const float* bg = &bias_g[r * HD + k0 + kk];
            a0.x = eluf(a0.x + bg[0]);  a0.y = eluf(a0.y + bg[1]);
            a0.z = eluf(a0.z + bg[2]);  a0.w = eluf(a0.w + bg[3]);
            a1.x = eluf(a1.x + bg[4]);  a1.y = eluf(a1.y + bg[5]);
            a1.z = eluf(a1.z + bg[6]);  a1.w = eluf(a1.w + bg[7]);
            *(float4*)zp = a0;  *(float4*)(zp + 4) = a1;   // z_r written in place
        }
        *(float4*)&As[rr * 36 + kk]     = a0;
        *(float4*)&As[rr * 36 + kk + 4] = a1;
        {
            int wr = t >> 3, wc = (t & 7) * 16;
            #pragma unroll
            for (int q = 0; q < 4; q++)
                *(float4*)&Ws[wr * 128 + wc + q * 4] =
                    *(const float4*)&W1[(k0 + wr) * 128 + wc + q * 4];
        }
        __syncthreads();
        #pragma unroll
        for (int k = 0; k < 32; k++) {
            float av[4];
            #pragma unroll
            for (int i = 0; i < 4; i++) av[i] = As[(ty * 4 + i) * 36 + k];
            float wv[8];
            *(float4*)&wv[0] = *(const float4*)&Ws[k * 128 + tx * 4];
            *(float4*)&wv[4] = *(const float4*)&Ws[k * 128 + 64 + tx * 4];
            #pragma unroll
            for (int i = 0; i < 4; i++)
                #pragma unroll
                for (int j = 0; j < 8; j++) acc[i][j] += av[i] * wv[j];
        }
        __syncthreads();
    }

    float b1v[8], w2v[8];
    #pragma unroll
    for (int j = 0; j < 4; j++) {
        int cA = tx * 4 + j, cB = 64 + tx * 4 + j;
        b1v[j]     = b1[cA];  w2v[j]     = W2[cA];
        b1v[4 + j] = b1[cB];  w2v[4 + j] = W2[cB];
    }
    float wpart = 0.f;
    #pragma unroll
    for (int i = 0; i < 4; i++) {
        float s = 0.f;
        #pragma unroll
        for (int j = 0; j < 8; j++) s += tanh_fast(acc[i][j] + b1v[j]) * w2v[j];
        s += __shfl_xor_sync(0xffffffffu, s, 1);
        s += __shfl_xor_sync(0xffffffffu, s, 2);
        s += __shfl_xor_sync(0xffffffffu, s, 4);
        s += __shfl_xor_sync(0xffffffffu, s, 8);
        int n = row0 + ty * 4 + i;
        if (tx == 0 && n < NN) wpart += s;
    }
    if (tx == 0) atomicAdd(&g_wsum[r], wpart);
}

// ---------------- K7: semantic softmax -------------------------------------
__global__ void k_softmax(float* __restrict__ out) {
    if (threadIdx.x == 0 && blockIdx.x == 0) {
        float w0 = g_wsum[0] / (float)NN;
        float w1 = g_wsum[1] / (float)NN;
        float w2 = g_wsum[2] / (float)NN;
        float m = fmaxf(w0, fmaxf(w1, w2));
        float e0 = expf(w0 - m), e1 = expf(w1 - m), e2 = expf(w2 - m);
        float s = e0 + e1 + e2;
        g_a[0] = e0 / s;  g_a[1] = e1 / s;  g_a[2] = e2 / s;
        out[(size_t)NN * HD + 0] = g_a[0];
        out[(size_t)NN * HD + 1] = g_a[1];
        out[(size_t)NN * HD + 2] = g_a[2];
    }
}

// ---------------- K8: z = sum_r a[r] * z_r ----------------------------------
__global__ void k_combine(float* __restrict__ out) {
    size_t i = blockIdx.x * (size_t)blockDim.x + threadIdx.x;
    size_t n4 = (size_t)NN * HD / 4;
    if (i >= n4) return;
    float a0 = g_a[0], a1 = g_a[1], a2 = g_a[2];
    const float4* z0 = (const float4*)g_rst;
    const float4* z1 = z0 + n4;
    const float4* z2 = z1 + n4;
    float4 x = z0[i], y = z1[i], z = z2[i];
    float4 o;
    o.x = a0 * x.x + a1 * y.x + a2 * z.x;
    o.y = a0 * x.y + a1 * y.y + a2 * z.y;
    o.z = a0 * x.z + a1 * y.z + a2 * z.z;
    o.w = a0 * x.w + a1 * y.w + a2 * z.w;
    ((float4*)out)[i] = o;
}

// ---------------- launcher --------------------------------------------------
extern "C" void kernel_launch(void* const* d_in, const int* in_sizes, int n_in,
                              void* d_out, int out_size) {
    const float* dst_feat  = (const float*)d_in[0];
    const float* src_feats = (const float*)d_in[1];
    const int*   src_idx   = (const int*)  d_in[2];
    const int*   dst_idx   = (const int*)  d_in[3];
    const float* Wt_dst    = (const float*)d_in[4];
    const float* bt_dst    = (const float*)d_in[5];
    const float* Wt_src    = (const float*)d_in[6];
    const float* bt_src    = (const float*)d_in[7];
    const float* Wg        = (const float*)d_in[8];
    const float* attn_l    = (const float*)d_in[9];
    const float* attn_r    = (const float*)d_in[10];
    const float* bias_g    = (const float*)d_in[11];
    const float* W1        = (const float*)d_in[12];
    const float* b1        = (const float*)d_in[13];
    const float* W2        = (const float*)d_in[14];
    float* out = (float*)d_out;

    k_prep<<<RR * 9, 256>>>(Wt_dst, bt_dst, Wt_src, bt_src, Wg, attn_r);
    k_fill<<<4096, 256>>>();
    k_gemm_hs<<<dim3((NN + 63) / 64, RR), 256>>>(src_feats, attn_l);
    k_er<<<(NN * 32 + 255) / 256, 256>>>(dst_feat);
    k_edge1<<<(RR * EE + 255) / 256, 256>>>(src_idx, dst_idx);
    k_edge2<<<(RR * EE * 32) / 256, 256>>>(src_idx, dst_idx);
    k_gemm_w<<<dim3((NN + 63) / 64, RR), 256>>>(bias_g, W1, b1, W2);
    k_softmax<<<1, 32>>>(out);
    k_combine<<<(NN * HD / 4 + 255) / 256, 256>>>(out);
}

// round 3
// speedup vs baseline: 1.5344x; 1.5344x over previous
#include <cuda_runtime.h>
#include <math.h>

#define NN   100000
#define RR   3
#define EE   320000
#define HIDF 128
#define HH   4
#define DDIM 32
#define HD   128

// ---------------- scratch (device globals; 16B aligned for v4 ops) ---------
__device__ __align__(16) float g_hs  [RR * NN * HD];
__device__ __align__(16) float g_rst [RR * NN * HD];
__device__ __align__(16) float g_el  [RR * NN * HH];
__device__ __align__(16) float g_er  [RR * NN * HH];
__device__ __align__(16) float g_ssum[RR * NN * HH];
__device__ __align__(16) float g_ex  [RR * EE * HH];
__device__ __align__(16) float g_Wcomb[RR * HIDF * HD];
__device__ __align__(16) float g_bcomb[RR * HD];
__device__ __align__(16) float g_Md  [RR * HIDF * HH];
__device__ __align__(16) float g_bd  [RR * HH];
__device__ __align__(16) float g_wsum[RR];
__device__ __align__(16) float g_a   [RR];

// ---------------- helpers --------------------------------------------------
__device__ __forceinline__ void red_add_v4(float* p, float4 v) {
    asm volatile("red.global.add.v4.f32 [%0], {%1,%2,%3,%4};"
                 :: "l"(p), "f"(v.x), "f"(v.y), "f"(v.z), "f"(v.w) : "memory");
}
__device__ __forceinline__ float tanh_fast(float x) {
    float y; asm("tanh.approx.f32 %0, %1;" : "=f"(y) : "f"(x)); return y;
}
__device__ __forceinline__ float eluf(float x) {
    return x > 0.f ? x : expm1f(x);
}
__device__ __forceinline__ unsigned f2tf(float x) {
    unsigned y; asm("cvt.rna.tf32.f32 %0, %1;" : "=r"(y) : "f"(x)); return y;
}
__device__ __forceinline__ void mma_tf32(float c[4], unsigned a0, unsigned a1,
                                         unsigned a2, unsigned a3,
                                         unsigned b0, unsigned b1) {
    asm volatile(
        "mma.sync.aligned.m16n8k8.row.col.f32.tf32.tf32.f32 "
        "{%0,%1,%2,%3}, {%4,%5,%6,%7}, {%8,%9}, {%0,%1,%2,%3};"
        : "+f"(c[0]), "+f"(c[1]), "+f"(c[2]), "+f"(c[3])
        : "r"(a0), "r"(a1), "r"(a2), "r"(a3), "r"(b0), "r"(b1));
}

// ---------------- K0: combined weights -------------------------------------
__global__ void k_prep(const float* __restrict__ Wt_dst, const float* __restrict__ bt_dst,
                       const float* __restrict__ Wt_src, const float* __restrict__ bt_src,
                       const float* __restrict__ Wg,     const float* __restrict__ attn_r) {
    int r = blockIdx.x / 9;
    int part = blockIdx.x % 9;
    int t = threadIdx.x; // 256
    const float* wg = Wg + r * HIDF * HD;
    if (part < 8) {
        const float* wts = Wt_src + r * HIDF * HIDF;
        #pragma unroll 1
        for (int it = 0; it < 8; it++) {
            int idx = part * 2048 + it * 256 + t;
            int f = idx >> 7, j = idx & 127;
            float s = 0.f;
            for (int g = 0; g < HIDF; g++)
                s += wts[f * HIDF + g] * wg[g * HD + j];
            g_Wcomb[r * HIDF * HD + idx] = s;
        }
    } else {
        __shared__ float ur[HIDF * HH];
        const float* ar = attn_r + r * HH * DDIM;
        for (int i = t; i < HIDF * HH; i += 256) {
            int f = i >> 2, h = i & 3;
            float s = 0.f;
            for (int d = 0; d < DDIM; d++)
                s += wg[f * HD + h * DDIM + d] * ar[h * DDIM + d];
            ur[i] = s;
        }
        __syncthreads();
        for (int i = t; i < HIDF * HH; i += 256) {
            int f = i >> 2, h = i & 3;
            float s = 0.f;
            for (int g = 0; g < HIDF; g++)
                s += Wt_dst[f * HIDF + g] * ur[g * HH + h];
            g_Md[r * HIDF * HH + i] = s;
        }
        if (t < HH) {
            float s = 0.f;
            for (int g = 0; g < HIDF; g++) s += bt_dst[g] * ur[g * HH + t];
            g_bd[r * HH + t] = s;
        }
        if (t < HD) {
            const float* bts = bt_src + r * HIDF;
            float s = 0.f;
            for (int f = 0; f < HIDF; f++) s += bts[f] * wg[f * HD + t];
            g_bcomb[r * HD + t] = s;
        }
    }
}

// ---------------- K1: zero accumulators ------------------------------------
__global__ void k_fill() {
    size_t i = blockIdx.x * (size_t)blockDim.x + threadIdx.x;
    size_t stride = gridDim.x * (size_t)blockDim.x;
    float4 z4 = {0.f, 0.f, 0.f, 0.f};
    size_t n4 = ((size_t)RR * NN * HD) / 4;
    for (size_t k = i; k < n4; k += stride) ((float4*)g_rst)[k] = z4;
    size_t m4 = ((size_t)RR * NN * HH) / 4;
    for (size_t k = i; k < m4; k += stride) ((float4*)g_ssum)[k] = z4;
    if (i < RR) g_wsum[i] = 0.f;
}

// ---------------- K2: hs = src @ Wcomb + bcomb (tf32 MMA) ; el epilogue -----
// Block 256 thr = 8 warps. Tile M=128, N=128, K chunks of 32.
// Warp wm=warp&3 (32 rows), wn=warp>>2 (64 cols). Per warp: 2x8 m16n8k8 tiles.
__global__ __launch_bounds__(256) void k_gemm_hs(const float* __restrict__ src_feats,
                                                 const float* __restrict__ attn_l) {
    __shared__ unsigned As[128 * 36];   // [row][k] tf32, pad 36
    __shared__ unsigned Ws[32 * 136];   // [k][col] tf32, pad 136
    const int r = blockIdx.y;
    const int row0 = blockIdx.x * 128;
    const int t = threadIdx.x;
    const int warp = t >> 5, lane = t & 31;
    const int wm = warp & 3, wn = warp >> 2;
    const int gid = lane >> 2, tid4 = lane & 3;
    const float* A = src_feats + (size_t)r * NN * HIDF;
    const float* W = g_Wcomb + r * HIDF * HD;

    float acc[2][8][4];
    #pragma unroll
    for (int mt = 0; mt < 2; mt++)
        #pragma unroll
        for (int nt = 0; nt < 8; nt++)
            #pragma unroll
            for (int q = 0; q < 4; q++) acc[mt][nt][q] = 0.f;

    for (int k0 = 0; k0 < HIDF; k0 += 32) {
        #pragma unroll
        for (int i = 0; i < 4; i++) {
            int idx = t + i * 256;
            int row = idx >> 3, kp = (idx & 7) * 4;
            float4 v = {0.f, 0.f, 0.f, 0.f};
            if (row0 + row < NN)
                v = *(const float4*)&A[(size_t)(row0 + row) * HIDF + k0 + kp];
            unsigned* p = &As[row * 36 + kp];
            p[0] = f2tf(v.x); p[1] = f2tf(v.y); p[2] = f2tf(v.z); p[3] = f2tf(v.w);
        }
        #pragma unroll
        for (int i = 0; i < 4; i++) {
            int idx = t + i * 256;
            int kr = idx >> 5, col = (idx & 31) * 4;
            float4 v = *(const float4*)&W[(k0 + kr) * HD + col];
            unsigned* p = &Ws[kr * 136 + col];
            p[0] = f2tf(v.x); p[1] = f2tf(v.y); p[2] = f2tf(v.z); p[3] = f2tf(v.w);
        }
        __syncthreads();
        #pragma unroll
        for (int ks = 0; ks < 4; ks++) {
            unsigned a[2][4];
            #pragma unroll
            for (int mt = 0; mt < 2; mt++) {
                int row = wm * 32 + mt * 16 + gid;
                a[mt][0] = As[row * 36 + ks * 8 + tid4];
                a[mt][1] = As[(row + 8) * 36 + ks * 8 + tid4];
                a[mt][2] = As[row * 36 + ks * 8 + tid4 + 4];
                a[mt][3] = As[(row + 8) * 36 + ks * 8 + tid4 + 4];
            }
            #pragma unroll
            for (int nt = 0; nt < 8; nt++) {
                int col = wn * 64 + nt * 8 + gid;
                unsigned b0 = Ws[(ks * 8 + tid4) * 136 + col];
                unsigned b1 = Ws[(ks * 8 + tid4 + 4) * 136 + col];
                mma_tf32(acc[0][nt], a[0][0], a[0][1], a[0][2], a[0][3], b0, b1);
                mma_tf32(acc[1][nt], a[1][0], a[1][1], a[1][2], a[1][3], b0, b1);
            }
        }
        __syncthreads();
    }

    // epilogue: +bcomb, store hs, head-partials el (head = wn*2 + (nt>=4))
    float2 alv[8], bcv[8];
    #pragma unroll
    for (int nt = 0; nt < 8; nt++) {
        int col = wn * 64 + nt * 8 + tid4 * 2;
        alv[nt] = *(const float2*)&attn_l[r * HD + col];
        bcv[nt] = *(const float2*)&g_bcomb[r * HD + col];
    }
    #pragma unroll
    for (int mt = 0; mt < 2; mt++) {
        int rbase = row0 + wm * 32 + mt * 16;
        int rowA = rbase + gid, rowB = rbase + gid + 8;
        float p0[2] = {0.f, 0.f}, p1[2] = {0.f, 0.f};
        #pragma unroll
        for (int nt = 0; nt < 8; nt++) {
            int half = nt >> 2;
            float v0 = acc[mt][nt][0] + bcv[nt].x;
            float v1 = acc[mt][nt][1] + bcv[nt].y;
            float v2 = acc[mt][nt][2] + bcv[nt].x;
            float v3 = acc[mt][nt][3] + bcv[nt].y;
            p0[half] += v0 * alv[nt].x + v1 * alv[nt].y;
            p1[half] += v2 * alv[nt].x + v3 * alv[nt].y;
            int col = wn * 64 + nt * 8 + tid4 * 2;
            if (rowA < NN)
                *(float2*)&g_hs[((size_t)r * NN + rowA) * HD + col] = make_float2(v0, v1);
            if (rowB < NN)
                *(float2*)&g_hs[((size_t)r * NN + rowB) * HD + col] = make_float2(v2, v3);
        }
        #pragma unroll
        for (int hh = 0; hh < 2; hh++) {
            p0[hh] += __shfl_xor_sync(0xffffffffu, p0[hh], 1);
            p0[hh] += __shfl_xor_sync(0xffffffffu, p0[hh], 2);
            p1[hh] += __shfl_xor_sync(0xffffffffu, p1[hh], 1);
            p1[hh] += __shfl_xor_sync(0xffffffffu, p1[hh], 2);
        }
        if (tid4 == 0) {
            if (rowA < NN) {
                g_el[((size_t)r * NN + rowA) * HH + wn * 2 + 0] = p0[0];
                g_el[((size_t)r * NN + rowA) * HH + wn * 2 + 1] = p0[1];
            }
            if (rowB < NN) {
                g_el[((size_t)r * NN + rowB) * HH + wn * 2 + 0] = p1[0];
                g_el[((size_t)r * NN + rowB) * HH + wn * 2 + 1] = p1[1];
            }
        }
    }
}

// ---------------- K3: er = dst_feat @ Md + bd (Md staged in smem) -----------
__global__ __launch_bounds__(256) void k_er(const float* __restrict__ dst_feat) {
    __shared__ float md[RR * HH * HIDF];   // [r][h][f]
    int t = threadIdx.x;
    #pragma unroll
    for (int i = 0; i < 6; i++) {
        int idx = t + i * 256;             // 1536 total
        int r = idx / (HH * HIDF);
        int rem = idx - r * (HH * HIDF);
        int h = rem >> 7, f = rem & 127;
        md[idx] = g_Md[r * HIDF * HH + f * HH + h];
    }
    __syncthreads();
    int warp = (blockIdx.x * 256 + t) >> 5;
    int lane = t & 31;
    if (warp >= NN) return;
    float4 fv = *(const float4*)&dst_feat[(size_t)warp * HIDF + lane * 4];
    float acc[RR * HH];
    #pragma unroll
    for (int rh = 0; rh < RR * HH; rh++) {
        float4 m = *(const float4*)&md[rh * HIDF + lane * 4];
        acc[rh] = fv.x * m.x + fv.y * m.y + fv.z * m.z + fv.w * m.w;
    }
    #pragma unroll
    for (int rh = 0; rh < RR * HH; rh++) {
        float v = acc[rh];
        v += __shfl_xor_sync(0xffffffffu, v, 16);
        v += __shfl_xor_sync(0xffffffffu, v, 8);
        v += __shfl_xor_sync(0xffffffffu, v, 4);
        v += __shfl_xor_sync(0xffffffffu, v, 2);
        v += __shfl_xor_sync(0xffffffffu, v, 1);
        acc[rh] = v;
    }
    if (lane < RR * HH) {
        int r = lane >> 2, h = lane & 3;
        g_er[((size_t)r * NN + warp) * HH + h] = acc[lane] + g_bd[lane];
    }
}

// ---------------- K4: edge scores ------------------------------------------
__global__ void k_edge1(const int* __restrict__ src_idx, const int* __restrict__ dst_idx) {
    int idx = blockIdx.x * blockDim.x + threadIdx.x;
    if (idx >= RR * EE) return;
    int rel = idx / EE;
    int s = src_idx[idx], d = dst_idx[idx];
    float4 l  = *(const float4*)&g_el[((size_t)rel * NN + s) * HH];
    float4 rv = *(const float4*)&g_er[((size_t)rel * NN + d) * HH];
    float x0 = l.x + rv.x, x1 = l.y + rv.y, x2 = l.z + rv.z, x3 = l.w + rv.w;
    x0 = x0 > 0.f ? x0 : 0.2f * x0;
    x1 = x1 > 0.f ? x1 : 0.2f * x1;
    x2 = x2 > 0.f ? x2 : 0.2f * x2;
    x3 = x3 > 0.f ? x3 : 0.2f * x3;
    float4 ex = {__expf(x0), __expf(x1), __expf(x2), __expf(x3)};
    *(float4*)&g_ex[(size_t)idx * 4] = ex;
    red_add_v4(&g_ssum[((size_t)rel * NN + d) * HH], ex);
}

// ---------------- K5: aggregation ------------------------------------------
__global__ void k_edge2(const int* __restrict__ src_idx, const int* __restrict__ dst_idx) {
    int gw = (blockIdx.x * blockDim.x + threadIdx.x) >> 5;
    if (gw >= RR * EE) return;
    int lane = threadIdx.x & 31;
    int rel = gw / EE;
    int s = src_idx[gw], d = dst_idx[gw];
    int h = lane >> 3;
    float exv = g_ex[(size_t)gw * 4 + h];
    float sv  = g_ssum[((size_t)rel * NN + d) * HH + h];
    float alpha = exv / (sv + 1e-9f);
    float4 v = *(const float4*)&g_hs[((size_t)rel * NN + s) * HD + lane * 4];
    v.x *= alpha; v.y *= alpha; v.z *= alpha; v.w *= alpha;
    red_add_v4(&g_rst[((size_t)rel * NN + d) * HD + lane * 4], v);
}

// ---------------- K6: z=elu(rst+bias) in place; wsum += tanh(z@W1+b1)@W2 ----
__global__ __launch_bounds__(256) void k_gemm_w(const float* __restrict__ bias_g,
                                                const float* __restrict__ W1,
                                                const float* __restrict__ b1,
                                                const float* __restrict__ W2) {
    __shared__ unsigned As[128 * 36];
    __shared__ unsigned Ws[32 * 136];
    const int r = blockIdx.y;
    const int row0 = blockIdx.x * 128;
    const int t = threadIdx.x;
    const int warp = t >> 5, lane = t & 31;
    const int wm = warp & 3, wn = warp >> 2;
    const int gid = lane >> 2, tid4 = lane & 3;
    float* Z = g_rst + (size_t)r * NN * HD;

    float acc[2][8][4];
    #pragma unroll
    for (int mt = 0; mt < 2; mt++)
        #pragma unroll
        for (int nt = 0; nt < 8; nt++)
            #pragma unroll
            for (int q = 0; q < 4; q++) acc[mt][nt][q] = 0.f;

    for (int k0 = 0; k0 < HD; k0 += 32) {
        #pragma unroll
        for (int i = 0; i < 4; i++) {
            int idx = t + i * 256;
            int row = idx >> 3, kp = (idx & 7) * 4;
            float4 v = {0.f, 0.f, 0.f, 0.f};
            int grow = row0 + row;
            if (grow < NN) {
                float* zp = &Z[(size_t)grow * HD + k0 + kp];
                v = *(float4*)zp;
                const float* bg = &bias_g[r * HD + k0 + kp];
                v.x = eluf(v.x + bg[0]); v.y = eluf(v.y + bg[1]);
                v.z = eluf(v.z + bg[2]); v.w = eluf(v.w + bg[3]);
                *(float4*)zp = v;      // z_r written in place for k_combine
            }
            unsigned* p = &As[row * 36 + kp];
            p[0] = f2tf(v.x); p[1] = f2tf(v.y); p[2] = f2tf(v.z); p[3] = f2tf(v.w);
        }
        #pragma unroll
        for (int i = 0; i < 4; i++) {
            int idx = t + i * 256;
            int kr = idx >> 5, col = (idx & 31) * 4;
            float4 v = *(const float4*)&W1[(k0 + kr) * 128 + col];
            unsigned* p = &Ws[kr * 136 + col];
            p[0] = f2tf(v.x); p[1] = f2tf(v.y); p[2] = f2tf(v.z); p[3] = f2tf(v.w);
        }
        __syncthreads();
        #pragma unroll
        for (int ks = 0; ks < 4; ks++) {
            unsigned a[2][4];
            #pragma unroll
            for (int mt = 0; mt < 2; mt++) {
                int row = wm * 32 + mt * 16 + gid;
                a[mt][0] = As[row * 36 + ks * 8 + tid4];
                a[mt][1] = As[(row + 8) * 36 + ks * 8 + tid4];
                a[mt][2] = As[row * 36 + ks * 8 + tid4 + 4];
                a[mt][3] = As[(row + 8) * 36 + ks * 8 + tid4 + 4];
            }
            #pragma unroll
            for (int nt = 0; nt < 8; nt++) {
                int col = wn * 64 + nt * 8 + gid;
                unsigned b0 = Ws[(ks * 8 + tid4) * 136 + col];
                unsigned b1 = Ws[(ks * 8 + tid4 + 4) * 136 + col];
                mma_tf32(acc[0][nt], a[0][0], a[0][1], a[0][2], a[0][3], b0, b1);
                mma_tf32(acc[1][nt], a[1][0], a[1][1], a[1][2], a[1][3], b0, b1);
            }
        }
        __syncthreads();
    }

    float2 b1v[8], w2v[8];
    #pragma unroll
    for (int nt = 0; nt < 8; nt++) {
        int col = wn * 64 + nt * 8 + tid4 * 2;
        b1v[nt] = *(const float2*)&b1[col];
        w2v[nt] = *(const float2*)&W2[col];
    }
    float wpart = 0.f;
    #pragma unroll
    for (int mt = 0; mt < 2; mt++) {
        int rbase = row0 + wm * 32 + mt * 16;
        float s0 = 0.f, s1 = 0.f;
        #pragma unroll
        for (int nt = 0; nt < 8; nt++) {
            s0 += tanh_fast(acc[mt][nt][0] + b1v[nt].x) * w2v[nt].x
                + tanh_fast(acc[mt][nt][1] + b1v[nt].y) * w2v[nt].y;
            s1 += tanh_fast(acc[mt][nt][2] + b1v[nt].x) * w2v[nt].x
                + tanh_fast(acc[mt][nt][3] + b1v[nt].y) * w2v[nt].y;
        }
        s0 += __shfl_xor_sync(0xffffffffu, s0, 1);
        s0 += __shfl_xor_sync(0xffffffffu, s0, 2);
        s1 += __shfl_xor_sync(0xffffffffu, s1, 1);
        s1 += __shfl_xor_sync(0xffffffffu, s1, 2);
        if (tid4 == 0) {
            if (rbase + gid < NN)     wpart += s0;
            if (rbase + gid + 8 < NN) wpart += s1;
        }
    }
    wpart += __shfl_xor_sync(0xffffffffu, wpart, 4);
    wpart += __shfl_xor_sync(0xffffffffu, wpart, 8);
    wpart += __shfl_xor_sync(0xffffffffu, wpart, 16);
    if (lane == 0) atomicAdd(&g_wsum[r], wpart);
}

// ---------------- K7: semantic softmax -------------------------------------
__global__ void k_softmax(float* __restrict__ out) {
    if (threadIdx.x == 0 && blockIdx.x == 0) {
        float w0 = g_wsum[0] / (float)NN;
        float w1 = g_wsum[1] / (float)NN;
        float w2 = g_wsum[2] / (float)NN;
        float m = fmaxf(w0, fmaxf(w1, w2));
        float e0 = expf(w0 - m), e1 = expf(w1 - m), e2 = expf(w2 - m);
        float s = e0 + e1 + e2;
        g_a[0] = e0 / s;  g_a[1] = e1 / s;  g_a[2] = e2 / s;
        out[(size_t)NN * HD + 0] = g_a[0];
        out[(size_t)NN * HD + 1] = g_a[1];
        out[(size_t)NN * HD + 2] = g_a[2];
    }
}

// ---------------- K8: z = sum_r a[r] * z_r ----------------------------------
__global__ void k_combine(float* __restrict__ out) {
    size_t i = blockIdx.x * (size_t)blockDim.x + threadIdx.x;
    size_t n4 = (size_t)NN * HD / 4;
    if (i >= n4) return;
    float a0 = g_a[0], a1 = g_a[1], a2 = g_a[2];
    const float4* z0 = (const float4*)g_rst;
    const float4* z1 = z0 + n4;
    const float4* z2 = z1 + n4;
    float4 x = z0[i], y = z1[i], z = z2[i];
    float4 o;
    o.x = a0 * x.x + a1 * y.x + a2 * z.x;
    o.y = a0 * x.y + a1 * y.y + a2 * z.y;
    o.z = a0 * x.z + a1 * y.z + a2 * z.z;
    o.w = a0 * x.w + a1 * y.w + a2 * z.w;
    ((float4*)out)[i] = o;
}

// ---------------- launcher --------------------------------------------------
extern "C" void kernel_launch(void* const* d_in, const int* in_sizes, int n_in,
                              void* d_out, int out_size) {
    const float* dst_feat  = (const float*)d_in[0];
    const float* src_feats = (const float*)d_in[1];
    const int*   src_idx   = (const int*)  d_in[2];
    const int*   dst_idx   = (const int*)  d_in[3];
    const float* Wt_dst    = (const float*)d_in[4];
    const float* bt_dst    = (const float*)d_in[5];
    const float* Wt_src    = (const float*)d_in[6];
    const float* bt_src    = (const float*)d_in[7];
    const float* Wg        = (const float*)d_in[8];
    const float* attn_l    = (const float*)d_in[9];
    const float* attn_r    = (const float*)d_in[10];
    const float* bias_g    = (const float*)d_in[11];
    const float* W1        = (const float*)d_in[12];
    const float* b1        = (const float*)d_in[13];
    const float* W2        = (const float*)d_in[14];
    float* out = (float*)d_out;

    k_prep<<<RR * 9, 256>>>(Wt_dst, bt_dst, Wt_src, bt_src, Wg, attn_r);
    k_fill<<<4096, 256>>>();
    k_gemm_hs<<<dim3((NN + 127) / 128, RR), 256>>>(src_feats, attn_l);
    k_er<<<(NN * 32 + 255) / 256, 256>>>(dst_feat);
    k_edge1<<<(RR * EE + 255) / 256, 256>>>(src_idx, dst_idx);
    k_edge2<<<(RR * EE * 32) / 256, 256>>>(src_idx, dst_idx);
    k_gemm_w<<<dim3((NN + 127) / 128, RR), 256>>>(bias_g, W1, b1, W2);
    k_softmax<<<1, 32>>>(out);
    k_combine<<<(NN * HD / 4 + 255) / 256, 256>>>(out);
}

// round 5
// speedup vs baseline: 1.5543x; 1.0130x over previous
#include <cuda_runtime.h>
#include <math.h>

#define NN   100000
#define RR   3
#define EE   320000
#define HIDF 128
#define HH   4
#define DDIM 32
#define HD   128

// ---------------- scratch (device globals; 16B aligned for v4 ops) ---------
__device__ __align__(16) float g_hs  [RR * NN * HD];
__device__ __align__(16) float g_rst [RR * NN * HD];
__device__ __align__(16) float g_el  [RR * NN * HH];
__device__ __align__(16) float g_er  [RR * NN * HH];
__device__ __align__(16) float g_ssum[RR * NN * HH];
__device__ __align__(16) float g_ex  [RR * EE * HH];
__device__ __align__(16) float g_Wcomb[RR * HIDF * HD];
__device__ __align__(16) float g_bcomb[RR * HD];
__device__ __align__(16) float g_Md  [RR * HIDF * HH];
__device__ __align__(16) float g_bd  [RR * HH];
__device__ __align__(16) float g_wsum[RR];
__device__ __align__(16) float g_a   [RR];

// ---------------- helpers --------------------------------------------------
__device__ __forceinline__ void red_add_v4(float* p, float4 v) {
    asm volatile("red.global.add.v4.f32 [%0], {%1,%2,%3,%4};"
                 :: "l"(p), "f"(v.x), "f"(v.y), "f"(v.z), "f"(v.w) : "memory");
}
__device__ __forceinline__ float tanh_fast(float x) {
    float y; asm("tanh.approx.f32 %0, %1;" : "=f"(y) : "f"(x)); return y;
}
__device__ __forceinline__ float eluf(float x) {
    return x > 0.f ? x : expm1f(x);
}
__device__ __forceinline__ unsigned f2tf(float x) {
    unsigned y; asm("cvt.rna.tf32.f32 %0, %1;" : "=r"(y) : "f"(x)); return y;
}
__device__ __forceinline__ void mma_tf32(float c[4], unsigned a0, unsigned a1,
                                         unsigned a2, unsigned a3,
                                         unsigned b0, unsigned b1) {
    asm volatile(
        "mma.sync.aligned.m16n8k8.row.col.f32.tf32.tf32.f32 "
        "{%0,%1,%2,%3}, {%4,%5,%6,%7}, {%8,%9}, {%0,%1,%2,%3};"
        : "+f"(c[0]), "+f"(c[1]), "+f"(c[2]), "+f"(c[3])
        : "r"(a0), "r"(a1), "r"(a2), "r"(a3), "r"(b0), "r"(b1));
}

// ---------------- K0: combined weights -------------------------------------
__global__ void k_prep(const float* __restrict__ Wt_dst, const float* __restrict__ bt_dst,
                       const float* __restrict__ Wt_src, const float* __restrict__ bt_src,
                       const float* __restrict__ Wg,     const float* __restrict__ attn_r) {
    int r = blockIdx.x / 9;
    int part = blockIdx.x % 9;
    int t = threadIdx.x; // 256
    const float* wg = Wg + r * HIDF * HD;
    if (part < 8) {
        const float* wts = Wt_src + r * HIDF * HIDF;
        #pragma unroll 1
        for (int it = 0; it < 8; it++) {
            int idx = part * 2048 + it * 256 + t;
            int f = idx >> 7, j = idx & 127;
            float s = 0.f;
            for (int g = 0; g < HIDF; g++)
                s += wts[f * HIDF + g] * wg[g * HD + j];
            g_Wcomb[r * HIDF * HD + idx] = s;
        }
    } else {
        __shared__ float ur[HIDF * HH];
        const float* ar = attn_r + r * HH * DDIM;
        for (int i = t; i < HIDF * HH; i += 256) {
            int f = i >> 2, h = i & 3;
            float s = 0.f;
            for (int d = 0; d < DDIM; d++)
                s += wg[f * HD + h * DDIM + d] * ar[h * DDIM + d];
            ur[i] = s;
        }
        __syncthreads();
        for (int i = t; i < HIDF * HH; i += 256) {
            int f = i >> 2, h = i & 3;
            float s = 0.f;
            for (int g = 0; g < HIDF; g++)
                s += Wt_dst[f * HIDF + g] * ur[g * HH + h];
            g_Md[r * HIDF * HH + i] = s;
        }
        if (t < HH) {
            float s = 0.f;
            for (int g = 0; g < HIDF; g++) s += bt_dst[g] * ur[g * HH + t];
            g_bd[r * HH + t] = s;
        }
        if (t < HD) {
            const float* bts = bt_src + r * HIDF;
            float s = 0.f;
            for (int f = 0; f < HIDF; f++) s += bts[f] * wg[f * HD + t];
            g_bcomb[r * HD + t] = s;
        }
    }
}

// ---------------- K1: zero accumulators ------------------------------------
__global__ void k_fill() {
    size_t i = blockIdx.x * (size_t)blockDim.x + threadIdx.x;
    size_t stride = gridDim.x * (size_t)blockDim.x;
    float4 z4 = {0.f, 0.f, 0.f, 0.f};
    size_t n4 = ((size_t)RR * NN * HD) / 4;
    for (size_t k = i; k < n4; k += stride) ((float4*)g_rst)[k] = z4;
    size_t m4 = ((size_t)RR * NN * HH) / 4;
    for (size_t k = i; k < m4; k += stride) ((float4*)g_ssum)[k] = z4;
    if (i < RR) g_wsum[i] = 0.f;
}

// ---------------- K2: hs = src @ Wcomb + bcomb (tf32 MMA) ; el epilogue -----
__global__ __launch_bounds__(256) void k_gemm_hs(const float* __restrict__ src_feats,
                                                 const float* __restrict__ attn_l) {
    __shared__ unsigned As[128 * 36];   // [row][k] tf32, pad 36
    __shared__ unsigned Ws[32 * 136];   // [k][col] tf32, pad 136
    const int r = blockIdx.y;
    const int row0 = blockIdx.x * 128;
    const int t = threadIdx.x;
    const int warp = t >> 5, lane = t & 31;
    const int wm = warp & 3, wn = warp >> 2;
    const int gid = lane >> 2, tid4 = lane & 3;
    const float* A = src_feats + (size_t)r * NN * HIDF;
    const float* W = g_Wcomb + r * HIDF * HD;

    float acc[2][8][4];
    #pragma unroll
    for (int mt = 0; mt < 2; mt++)
        #pragma unroll
        for (int nt = 0; nt < 8; nt++)
            #pragma unroll
            for (int q = 0; q < 4; q++) acc[mt][nt][q] = 0.f;

    for (int k0 = 0; k0 < HIDF; k0 += 32) {
        #pragma unroll
        for (int i = 0; i < 4; i++) {
            int idx = t + i * 256;
            int row = idx >> 3, kp = (idx & 7) * 4;
            float4 v = {0.f, 0.f, 0.f, 0.f};
            if (row0 + row < NN)
                v = *(const float4*)&A[(size_t)(row0 + row) * HIDF + k0 + kp];
            unsigned* p = &As[row * 36 + kp];
            p[0] = f2tf(v.x); p[1] = f2tf(v.y); p[2] = f2tf(v.z); p[3] = f2tf(v.w);
        }
        #pragma unroll
        for (int i = 0; i < 4; i++) {
            int idx = t + i * 256;
            int kr = idx >> 5, col = (idx & 31) * 4;
            float4 v = *(const float4*)&W[(k0 + kr) * HD + col];
            unsigned* p = &Ws[kr * 136 + col];
            p[0] = f2tf(v.x); p[1] = f2tf(v.y); p[2] = f2tf(v.z); p[3] = f2tf(v.w);
        }
        __syncthreads();
        #pragma unroll
        for (int ks = 0; ks < 4; ks++) {
            unsigned a[2][4];
            #pragma unroll
            for (int mt = 0; mt < 2; mt++) {
                int row = wm * 32 + mt * 16 + gid;
                a[mt][0] = As[row * 36 + ks * 8 + tid4];
                a[mt][1] = As[(row + 8) * 36 + ks * 8 + tid4];
                a[mt][2] = As[row * 36 + ks * 8 + tid4 + 4];
                a[mt][3] = As[(row + 8) * 36 + ks * 8 + tid4 + 4];
            }
            #pragma unroll
            for (int nt = 0; nt < 8; nt++) {
                int col = wn * 64 + nt * 8 + gid;
                unsigned b0 = Ws[(ks * 8 + tid4) * 136 + col];
                unsigned b1 = Ws[(ks * 8 + tid4 + 4) * 136 + col];
                mma_tf32(acc[0][nt], a[0][0], a[0][1], a[0][2], a[0][3], b0, b1);
                mma_tf32(acc[1][nt], a[1][0], a[1][1], a[1][2], a[1][3], b0, b1);
            }
        }
        __syncthreads();
    }

    float2 alv[8], bcv[8];
    #pragma unroll
    for (int nt = 0; nt < 8; nt++) {
        int col = wn * 64 + nt * 8 + tid4 * 2;
        alv[nt] = *(const float2*)&attn_l[r * HD + col];
        bcv[nt] = *(const float2*)&g_bcomb[r * HD + col];
    }
    #pragma unroll
    for (int mt = 0; mt < 2; mt++) {
        int rbase = row0 + wm * 32 + mt * 16;
        int rowA = rbase + gid, rowB = rbase + gid + 8;
        float p0[2] = {0.f, 0.f}, p1[2] = {0.f, 0.f};
        #pragma unroll
        for (int nt = 0; nt < 8; nt++) {
            int half = nt >> 2;
            float v0 = acc[mt][nt][0] + bcv[nt].x;
            float v1 = acc[mt][nt][1] + bcv[nt].y;
            float v2 = acc[mt][nt][2] + bcv[nt].x;
            float v3 = acc[mt][nt][3] + bcv[nt].y;
            p0[half] += v0 * alv[nt].x + v1 * alv[nt].y;
            p1[half] += v2 * alv[nt].x + v3 * alv[nt].y;
            int col = wn * 64 + nt * 8 + tid4 * 2;
            if (rowA < NN)
                *(float2*)&g_hs[((size_t)r * NN + rowA) * HD + col] = make_float2(v0, v1);
            if (rowB < NN)
                *(float2*)&g_hs[((size_t)r * NN + rowB) * HD + col] = make_float2(v2, v3);
        }
        #pragma unroll
        for (int hh = 0; hh < 2; hh++) {
            p0[hh] += __shfl_xor_sync(0xffffffffu, p0[hh], 1);
            p0[hh] += __shfl_xor_sync(0xffffffffu, p0[hh], 2);
            p1[hh] += __shfl_xor_sync(0xffffffffu, p1[hh], 1);
            p1[hh] += __shfl_xor_sync(0xffffffffu, p1[hh], 2);
        }
        if (tid4 == 0) {
            if (rowA < NN) {
                g_el[((size_t)r * NN + rowA) * HH + wn * 2 + 0] = p0[0];
                g_el[((size_t)r * NN + rowA) * HH + wn * 2 + 1] = p0[1];
            }
            if (rowB < NN) {
                g_el[((size_t)r * NN + rowB) * HH + wn * 2 + 0] = p1[0];
                g_el[((size_t)r * NN + rowB) * HH + wn * 2 + 1] = p1[1];
            }
        }
    }
}

// ---------------- K3: er = dst_feat @ Md + bd (Md in registers) -------------
// Warp-per-node, grid-stride. Each lane holds Md[rh][lane*4 .. +3] in regs.
__global__ __launch_bounds__(256) void k_er(const float* __restrict__ dst_feat) {
    const int lane = threadIdx.x & 31;
    const int gw = (blockIdx.x * 256 + threadIdx.x) >> 5;
    const int nw = gridDim.x * 8;

    float4 mdreg[RR * HH];
    #pragma unroll
    for (int rh = 0; rh < RR * HH; rh++) {
        int r = rh >> 2, h = rh & 3;
        const float* base = &g_Md[r * HIDF * HH + h];
        mdreg[rh].x = base[(4 * lane + 0) * HH];
        mdreg[rh].y = base[(4 * lane + 1) * HH];
        mdreg[rh].z = base[(4 * lane + 2) * HH];
        mdreg[rh].w = base[(4 * lane + 3) * HH];
    }
    const float bdv = (lane < RR * HH) ? g_bd[lane] : 0.f;
    const int lr = lane >> 2, lh = lane & 3;   // for scatter when lane<12

    for (int n = gw; n < NN; n += nw) {
        float4 f = *(const float4*)&dst_feat[(size_t)n * HIDF + lane * 4];
        float acc[RR * HH];
        #pragma unroll
        for (int rh = 0; rh < RR * HH; rh++)
            acc[rh] = f.x * mdreg[rh].x + f.y * mdreg[rh].y
                    + f.z * mdreg[rh].z + f.w * mdreg[rh].w;
        #pragma unroll
        for (int rh = 0; rh < RR * HH; rh++) {
            float v = acc[rh];
            v += __shfl_xor_sync(0xffffffffu, v, 16);
            v += __shfl_xor_sync(0xffffffffu, v, 8);
            v += __shfl_xor_sync(0xffffffffu, v, 4);
            v += __shfl_xor_sync(0xffffffffu, v, 2);
            v += __shfl_xor_sync(0xffffffffu, v, 1);
            acc[rh] = v;
        }
        #pragma unroll
        for (int rh = 0; rh < RR * HH; rh++) {
            if (lane == rh)
                g_er[((size_t)lr * NN + n) * HH + lh] = acc[rh] + bdv;
        }
    }
}

// ---------------- K4: edge scores ------------------------------------------
__global__ void k_edge1(const int* __restrict__ src_idx, const int* __restrict__ dst_idx) {
    int idx = blockIdx.x * blockDim.x + threadIdx.x;
    if (idx >= RR * EE) return;
    int rel = idx / EE;
    int s = src_idx[idx], d = dst_idx[idx];
    float4 l  = *(const float4*)&g_el[((size_t)rel * NN + s) * HH];
    float4 rv = *(const float4*)&g_er[((size_t)rel * NN + d) * HH];
    float x0 = l.x + rv.x, x1 = l.y + rv.y, x2 = l.z + rv.z, x3 = l.w + rv.w;
    x0 = x0 > 0.f ? x0 : 0.2f * x0;
    x1 = x1 > 0.f ? x1 : 0.2f * x1;
    x2 = x2 > 0.f ? x2 : 0.2f * x2;
    x3 = x3 > 0.f ? x3 : 0.2f * x3;
    float4 ex = {__expf(x0), __expf(x1), __expf(x2), __expf(x3)};
    *(float4*)&g_ex[(size_t)idx * 4] = ex;
    red_add_v4(&g_ssum[((size_t)rel * NN + d) * HH], ex);
}

// ---------------- K5: aggregation ------------------------------------------
__global__ void k_edge2(const int* __restrict__ src_idx, const int* __restrict__ dst_idx) {
    int gw = (blockIdx.x * blockDim.x + threadIdx.x) >> 5;
    if (gw >= RR * EE) return;
    int lane = threadIdx.x & 31;
    int rel = gw / EE;
    int s = src_idx[gw], d = dst_idx[gw];
    int h = lane >> 3;
    float exv = g_ex[(size_t)gw * 4 + h];
    float sv  = g_ssum[((size_t)rel * NN + d) * HH + h];
    float alpha = __fdividef(exv, sv + 1e-9f);
    float4 v = *(const float4*)&g_hs[((size_t)rel * NN + s) * HD + lane * 4];
    v.x *= alpha; v.y *= alpha; v.z *= alpha; v.w *= alpha;
    red_add_v4(&g_rst[((size_t)rel * NN + d) * HD + lane * 4], v);
}

// ---------------- K6: wsum += tanh(elu(rst+bias)@W1+b1)@W2 (no z write) -----
__global__ __launch_bounds__(256) void k_gemm_w(const float* __restrict__ bias_g,
                                                const float* __restrict__ W1,
                                                const float* __restrict__ b1,
                                                const float* __restrict__ W2) {
    __shared__ unsigned As[128 * 36];
    __shared__ unsigned Ws[32 * 136];
    const int r = blockIdx.y;
    const int row0 = blockIdx.x * 128;
    const int t = threadIdx.x;
    const int warp = t >> 5, lane = t & 31;
    const int wm = warp & 3, wn = warp >> 2;
    const int gid = lane >> 2, tid4 = lane & 3;
    const float* Z = g_rst + (size_t)r * NN * HD;

    float acc[2][8][4];
    #pragma unroll
    for (int mt = 0; mt < 2; mt++)
        #pragma unroll
        for (int nt = 0; nt < 8; nt++)
            #pragma unroll
            for (int q = 0; q < 4; q++) acc[mt][nt][q] = 0.f;

    for (int k0 = 0; k0 < HD; k0 += 32) {
        #pragma unroll
        for (int i = 0; i < 4; i++) {
            int idx = t + i * 256;
            int row = idx >> 3, kp = (idx & 7) * 4;
            float4 v = {0.f, 0.f, 0.f, 0.f};
            int grow = row0 + row;
            if (grow < NN) {
                v = *(const float4*)&Z[(size_t)grow * HD + k0 + kp];
                const float* bg = &bias_g[r * HD + k0 + kp];
                v.x = eluf(v.x + bg[0]); v.y = eluf(v.y + bg[1]);
                v.z = eluf(v.z + bg[2]); v.w = eluf(v.w + bg[3]);
            }
            unsigned* p = &As[row * 36 + kp];
            p[0] = f2tf(v.x); p[1] = f2tf(v.y); p[2] = f2tf(v.z); p[3] = f2tf(v.w);
        }
        #pragma unroll
        for (int i = 0; i < 4; i++) {
            int idx = t + i * 256;
            int kr = idx >> 5, col = (idx & 31) * 4;
            float4 v = *(const float4*)&W1[(k0 + kr) * 128 + col];
            unsigned* p = &Ws[kr * 136 + col];
            p[0] = f2tf(v.x); p[1] = f2tf(v.y); p[2] = f2tf(v.z); p[3] = f2tf(v.w);
        }
        __syncthreads();
        #pragma unroll
        for (int ks = 0; ks < 4; ks++) {
            unsigned a[2][4];
            #pragma unroll
            for (int mt = 0; mt < 2; mt++) {
                int row = wm * 32 + mt * 16 + gid;
                a[mt][0] = As[row * 36 + ks * 8 + tid4];
                a[mt][1] = As[(row + 8) * 36 + ks * 8 + tid4];
                a[mt][2] = As[row * 36 + ks * 8 + tid4 + 4];
                a[mt][3] = As[(row + 8) * 36 + ks * 8 + tid4 + 4];
            }
            #pragma unroll
            for (int nt = 0; nt < 8; nt++) {
                int col = wn * 64 + nt * 8 + gid;
                unsigned b0 = Ws[(ks * 8 + tid4) * 136 + col];
                unsigned b1 = Ws[(ks * 8 + tid4 + 4) * 136 + col];
                mma_tf32(acc[0][nt], a[0][0], a[0][1], a[0][2], a[0][3], b0, b1);
                mma_tf32(acc[1][nt], a[1][0], a[1][1], a[1][2], a[1][3], b0, b1);
            }
        }
        __syncthreads();
    }

    float2 b1v[8], w2v[8];
    #pragma unroll
    for (int nt = 0; nt < 8; nt++) {
        int col = wn * 64 + nt * 8 + tid4 * 2;
        b1v[nt] = *(const float2*)&b1[col];
        w2v[nt] = *(const float2*)&W2[col];
    }
    float wpart = 0.f;
    #pragma unroll
    for (int mt = 0; mt < 2; mt++) {
        int rbase = row0 + wm * 32 + mt * 16;
        float s0 = 0.f, s1 = 0.f;
        #pragma unroll
        for (int nt = 0; nt < 8; nt++) {
            s0 += tanh_fast(acc[mt][nt][0] + b1v[nt].x) * w2v[nt].x
                + tanh_fast(acc[mt][nt][1] + b1v[nt].y) * w2v[nt].y;
            s1 += tanh_fast(acc[mt][nt][2] + b1v[nt].x) * w2v[nt].x
                + tanh_fast(acc[mt][nt][3] + b1v[nt].y) * w2v[nt].y;
        }
        s0 += __shfl_xor_sync(0xffffffffu, s0, 1);
        s0 += __shfl_xor_sync(0xffffffffu, s0, 2);
        s1 += __shfl_xor_sync(0xffffffffu, s1, 1);
        s1 += __shfl_xor_sync(0xffffffffu, s1, 2);
        if (tid4 == 0) {
            if (rbase + gid < NN)     wpart += s0;
            if (rbase + gid + 8 < NN) wpart += s1;
        }
    }
    wpart += __shfl_xor_sync(0xffffffffu, wpart, 4);
    wpart += __shfl_xor_sync(0xffffffffu, wpart, 8);
    wpart += __shfl_xor_sync(0xffffffffu, wpart, 16);
    if (lane == 0) atomicAdd(&g_wsum[r], wpart);
}

// ---------------- K7: semantic softmax -------------------------------------
__global__ void k_softmax(float* __restrict__ out) {
    if (threadIdx.x == 0 && blockIdx.x == 0) {
        float w0 = g_wsum[0] / (float)NN;
        float w1 = g_wsum[1] / (float)NN;
        float w2 = g_wsum[2] / (float)NN;
        float m = fmaxf(w0, fmaxf(w1, w2));
        float e0 = expf(w0 - m), e1 = expf(w1 - m), e2 = expf(w2 - m);
        float s = e0 + e1 + e2;
        g_a[0] = e0 / s;  g_a[1] = e1 / s;  g_a[2] = e2 / s;
        out[(size_t)NN * HD + 0] = g_a[0];
        out[(size_t)NN * HD + 1] = g_a[1];
        out[(size_t)NN * HD + 2] = g_a[2];
    }
}

// ---------------- K8: z = sum_r a[r] * elu(rst_r + bias_r) -------------------
__global__ void k_combine(const float* __restrict__ bias_g, float* __restrict__ out) {
    size_t i = blockIdx.x * (size_t)blockDim.x + threadIdx.x;
    size_t n4 = (size_t)NN * HD / 4;
    if (i >= n4) return;
    int c = ((int)(i & 31)) * 4;         // column within 128-wide row
    float a0 = g_a[0], a1 = g_a[1], a2 = g_a[2];
    float4 bg0 = *(const float4*)&bias_g[0 * HD + c];
    float4 bg1 = *(const float4*)&bias_g[1 * HD + c];
    float4 bg2 = *(const float4*)&bias_g[2 * HD + c];
    const float4* z0 = (const float4*)g_rst;
    const float4* z1 = z0 + n4;
    const float4* z2 = z1 + n4;
    float4 x = z0[i], y = z1[i], z = z2[i];
    float4 o;
    o.x = a0 * eluf(x.x + bg0.x) + a1 * eluf(y.x + bg1.x) + a2 * eluf(z.x + bg2.x);
    o.y = a0 * eluf(x.y + bg0.y) + a1 * eluf(y.y + bg1.y) + a2 * eluf(z.y + bg2.y);
    o.z = a0 * eluf(x.z + bg0.z) + a1 * eluf(y.z + bg1.z) + a2 * eluf(z.z + bg2.z);
    o.w = a0 * eluf(x.w + bg0.w) + a1 * eluf(y.w + bg1.w) + a2 * eluf(z.w + bg2.w);
    ((float4*)out)[i] = o;
}

// ---------------- launcher --------------------------------------------------
extern "C" void kernel_launch(void* const* d_in, const int* in_sizes, int n_in,
                              void* d_out, int out_size) {
    const float* dst_feat  = (const float*)d_in[0];
    const float* src_feats = (const float*)d_in[1];
    const int*   src_idx   = (const int*)  d_in[2];
    const int*   dst_idx   = (const int*)  d_in[3];
    const float* Wt_dst    = (const float*)d_in[4];
    const float* bt_dst    = (const float*)d_in[5];
    const float* Wt_src    = (const float*)d_in[6];
    const float* bt_src    = (const float*)d_in[7];
    const float* Wg        = (const float*)d_in[8];
    const float* attn_l    = (const float*)d_in[9];
    const float* attn_r    = (const float*)d_in[10];
    const float* bias_g    = (const float*)d_in[11];
    const float* W1        = (const float*)d_in[12];
    const float* b1        = (const float*)d_in[13];
    const float* W2        = (const float*)d_in[14];
    float* out = (float*)d_out;

    k_prep<<<RR * 9, 256>>>(Wt_dst, bt_dst, Wt_src, bt_src, Wg, attn_r);
    k_fill<<<4096, 256>>>();
    k_gemm_hs<<<dim3((NN + 127) / 128, RR), 256>>>(src_feats, attn_l);
    k_er<<<800, 256>>>(dst_feat);
    k_edge1<<<(RR * EE + 255) / 256, 256>>>(src_idx, dst_idx);
    k_edge2<<<(RR * EE * 32) / 256, 256>>>(src_idx, dst_idx);
    k_gemm_w<<<dim3((NN + 127) / 128, RR), 256>>>(bias_g, W1, b1, W2);
    k_softmax<<<1, 32>>>(out);
    k_combine<<<(NN * HD / 4 + 255) / 256, 256>>>(bias_g, out);
}

// round 6
// speedup vs baseline: 1.7238x; 1.1091x over previous
#include <cuda_runtime.h>
#include <math.h>

#define NN   100000
#define RR   3
#define EE   320000
#define HIDF 128
#define HH   4
#define DDIM 32
#define HD   128

// ---------------- scratch (device globals; 16B aligned for v4 ops) ---------
__device__ __align__(16) float g_hs  [RR * NN * HD];
__device__ __align__(16) float g_rst [RR * NN * HD];
__device__ __align__(16) float g_el  [RR * NN * HH];
__device__ __align__(16) float g_er  [RR * NN * HH];
__device__ __align__(16) float g_ssum[RR * NN * HH];
__device__ __align__(16) float g_ex  [RR * EE * HH];
__device__ __align__(16) float g_Wcomb[RR * HIDF * HD];
__device__ __align__(16) float g_bcomb[RR * HD];
__device__ __align__(16) float g_Md  [RR * HIDF * HH];
__device__ __align__(16) float g_bd  [RR * HH];
__device__ __align__(16) float g_wsum[RR];
__device__ __align__(16) float g_a   [RR];

// ---------------- helpers --------------------------------------------------
__device__ __forceinline__ void red_add_v4(float* p, float4 v) {
    asm volatile("red.global.add.v4.f32 [%0], {%1,%2,%3,%4};"
                 :: "l"(p), "f"(v.x), "f"(v.y), "f"(v.z), "f"(v.w) : "memory");
}
__device__ __forceinline__ float tanh_fast(float x) {
    float y; asm("tanh.approx.f32 %0, %1;" : "=f"(y) : "f"(x)); return y;
}
__device__ __forceinline__ float eluf(float x) {
    return x > 0.f ? x : expm1f(x);
}
__device__ __forceinline__ unsigned f2tf(float x) {
    unsigned y; asm("cvt.rna.tf32.f32 %0, %1;" : "=r"(y) : "f"(x)); return y;
}
__device__ __forceinline__ void mma_tf32(float c[4], unsigned a0, unsigned a1,
                                         unsigned a2, unsigned a3,
                                         unsigned b0, unsigned b1) {
    asm volatile(
        "mma.sync.aligned.m16n8k8.row.col.f32.tf32.tf32.f32 "
        "{%0,%1,%2,%3}, {%4,%5,%6,%7}, {%8,%9}, {%0,%1,%2,%3};"
        : "+f"(c[0]), "+f"(c[1]), "+f"(c[2]), "+f"(c[3])
        : "r"(a0), "r"(a1), "r"(a2), "r"(a3), "r"(b0), "r"(b1));
}

// ---------------- K0: combined weights -------------------------------------
__global__ void k_prep(const float* __restrict__ Wt_dst, const float* __restrict__ bt_dst,
                       const float* __restrict__ Wt_src, const float* __restrict__ bt_src,
                       const float* __restrict__ Wg,     const float* __restrict__ attn_r) {
    int r = blockIdx.x / 9;
    int part = blockIdx.x % 9;
    int t = threadIdx.x; // 256
    const float* wg = Wg + r * HIDF * HD;
    if (part < 8) {
        const float* wts = Wt_src + r * HIDF * HIDF;
        #pragma unroll 1
        for (int it = 0; it < 8; it++) {
            int idx = part * 2048 + it * 256 + t;
            int f = idx >> 7, j = idx & 127;
            float s = 0.f;
            for (int g = 0; g < HIDF; g++)
                s += wts[f * HIDF + g] * wg[g * HD + j];
            g_Wcomb[r * HIDF * HD + idx] = s;
        }
    } else {
        __shared__ float ur[HIDF * HH];
        const float* ar = attn_r + r * HH * DDIM;
        for (int i = t; i < HIDF * HH; i += 256) {
            int f = i >> 2, h = i & 3;
            float s = 0.f;
            for (int d = 0; d < DDIM; d++)
                s += wg[f * HD + h * DDIM + d] * ar[h * DDIM + d];
            ur[i] = s;
        }
        __syncthreads();
        for (int i = t; i < HIDF * HH; i += 256) {
            int f = i >> 2, h = i & 3;
            float s = 0.f;
            for (int g = 0; g < HIDF; g++)
                s += Wt_dst[f * HIDF + g] * ur[g * HH + h];
            g_Md[r * HIDF * HH + i] = s;
        }
        if (t < HH) {
            float s = 0.f;
            for (int g = 0; g < HIDF; g++) s += bt_dst[g] * ur[g * HH + t];
            g_bd[r * HH + t] = s;
        }
        if (t < HD) {
            const float* bts = bt_src + r * HIDF;
            float s = 0.f;
            for (int f = 0; f < HIDF; f++) s += bts[f] * wg[f * HD + t];
            g_bcomb[r * HD + t] = s;
        }
    }
}

// ---------------- K1: zero accumulators ------------------------------------
__global__ void k_fill() {
    size_t i = blockIdx.x * (size_t)blockDim.x + threadIdx.x;
    size_t stride = gridDim.x * (size_t)blockDim.x;
    float4 z4 = {0.f, 0.f, 0.f, 0.f};
    size_t n4 = ((size_t)RR * NN * HD) / 4;
    for (size_t k = i; k < n4; k += stride) ((float4*)g_rst)[k] = z4;
    size_t m4 = ((size_t)RR * NN * HH) / 4;
    for (size_t k = i; k < m4; k += stride) ((float4*)g_ssum)[k] = z4;
    if (i < RR) g_wsum[i] = 0.f;
}

// ---------------- K2: hs = src @ Wcomb + bcomb (tf32 MMA) ; el epilogue -----
__global__ __launch_bounds__(256) void k_gemm_hs(const float* __restrict__ src_feats,
                                                 const float* __restrict__ attn_l) {
    __shared__ unsigned As[128 * 36];   // [row][k] tf32, pad 36
    __shared__ unsigned Ws[32 * 136];   // [k][col] tf32, pad 136
    const int r = blockIdx.y;
    const int row0 = blockIdx.x * 128;
    const int t = threadIdx.x;
    const int warp = t >> 5, lane = t & 31;
    const int wm = warp & 3, wn = warp >> 2;
    const int gid = lane >> 2, tid4 = lane & 3;
    const float* A = src_feats + (size_t)r * NN * HIDF;
    const float* W = g_Wcomb + r * HIDF * HD;

    float acc[2][8][4];
    #pragma unroll
    for (int mt = 0; mt < 2; mt++)
        #pragma unroll
        for (int nt = 0; nt < 8; nt++)
            #pragma unroll
            for (int q = 0; q < 4; q++) acc[mt][nt][q] = 0.f;

    for (int k0 = 0; k0 < HIDF; k0 += 32) {
        #pragma unroll
        for (int i = 0; i < 4; i++) {
            int idx = t + i * 256;
            int row = idx >> 3, kp = (idx & 7) * 4;
            float4 v = {0.f, 0.f, 0.f, 0.f};
            if (row0 + row < NN)
                v = *(const float4*)&A[(size_t)(row0 + row) * HIDF + k0 + kp];
            unsigned* p = &As[row * 36 + kp];
            p[0] = f2tf(v.x); p[1] = f2tf(v.y); p[2] = f2tf(v.z); p[3] = f2tf(v.w);
        }
        #pragma unroll
        for (int i = 0; i < 4; i++) {
            int idx = t + i * 256;
            int kr = idx >> 5, col = (idx & 31) * 4;
            float4 v = *(const float4*)&W[(k0 + kr) * HD + col];
            unsigned* p = &Ws[kr * 136 + col];
            p[0] = f2tf(v.x); p[1] = f2tf(v.y); p[2] = f2tf(v.z); p[3] = f2tf(v.w);
        }
        __syncthreads();
        #pragma unroll
        for (int ks = 0; ks < 4; ks++) {
            unsigned a[2][4];
            #pragma unroll
            for (int mt = 0; mt < 2; mt++) {
                int row = wm * 32 + mt * 16 + gid;
                a[mt][0] = As[row * 36 + ks * 8 + tid4];
                a[mt][1] = As[(row + 8) * 36 + ks * 8 + tid4];
                a[mt][2] = As[row * 36 + ks * 8 + tid4 + 4];
                a[mt][3] = As[(row + 8) * 36 + ks * 8 + tid4 + 4];
            }
            #pragma unroll
            for (int nt = 0; nt < 8; nt++) {
                int col = wn * 64 + nt * 8 + gid;
                unsigned b0 = Ws[(ks * 8 + tid4) * 136 + col];
                unsigned b1 = Ws[(ks * 8 + tid4 + 4) * 136 + col];
                mma_tf32(acc[0][nt], a[0][0], a[0][1], a[0][2], a[0][3], b0, b1);
                mma_tf32(acc[1][nt], a[1][0], a[1][1], a[1][2], a[1][3], b0, b1);
            }
        }
        __syncthreads();
    }

    float2 alv[8], bcv[8];
    #pragma unroll
    for (int nt = 0; nt < 8; nt++) {
        int col = wn * 64 + nt * 8 + tid4 * 2;
        alv[nt] = *(const float2*)&attn_l[r * HD + col];
        bcv[nt] = *(const float2*)&g_bcomb[r * HD + col];
    }
    #pragma unroll
    for (int mt = 0; mt < 2; mt++) {
        int rbase = row0 + wm * 32 + mt * 16;
        int rowA = rbase + gid, rowB = rbase + gid + 8;
        float p0[2] = {0.f, 0.f}, p1[2] = {0.f, 0.f};
        #pragma unroll
        for (int nt = 0; nt < 8; nt++) {
            int half = nt >> 2;
            float v0 = acc[mt][nt][0] + bcv[nt].x;
            float v1 = acc[mt][nt][1] + bcv[nt].y;
            float v2 = acc[mt][nt][2] + bcv[nt].x;
            float v3 = acc[mt][nt][3] + bcv[nt].y;
            p0[half] += v0 * alv[nt].x + v1 * alv[nt].y;
            p1[half] += v2 * alv[nt].x + v3 * alv[nt].y;
            int col = wn * 64 + nt * 8 + tid4 * 2;
            if (rowA < NN)
                *(float2*)&g_hs[((size_t)r * NN + rowA) * HD + col] = make_float2(v0, v1);
            if (rowB < NN)
                *(float2*)&g_hs[((size_t)r * NN + rowB) * HD + col] = make_float2(v2, v3);
        }
        #pragma unroll
        for (int hh = 0; hh < 2; hh++) {
            p0[hh] += __shfl_xor_sync(0xffffffffu, p0[hh], 1);
            p0[hh] += __shfl_xor_sync(0xffffffffu, p0[hh], 2);
            p1[hh] += __shfl_xor_sync(0xffffffffu, p1[hh], 1);
            p1[hh] += __shfl_xor_sync(0xffffffffu, p1[hh], 2);
        }
        if (tid4 == 0) {
            if (rowA < NN) {
                g_el[((size_t)r * NN + rowA) * HH + wn * 2 + 0] = p0[0];
                g_el[((size_t)r * NN + rowA) * HH + wn * 2 + 1] = p0[1];
            }
            if (rowB < NN) {
                g_el[((size_t)r * NN + rowB) * HH + wn * 2 + 0] = p1[0];
                g_el[((size_t)r * NN + rowB) * HH + wn * 2 + 1] = p1[1];
            }
        }
    }
}

// ---------------- K3: er = dst_feat @ Mdall + bd  (tf32 MMA, N=16 padded) ---
// Block: 256 thr / 8 warps, M-tile 128 rows, each warp one m16 tile x 2 n8.
__global__ __launch_bounds__(256) void k_er(const float* __restrict__ dst_feat) {
    __shared__ unsigned As[128 * 36];   // [row][k-chunk 32] tf32
    __shared__ unsigned Bs[128 * 16];   // [k][col] tf32, cols 0..11 used
    const int t = threadIdx.x;
    const int warp = t >> 5, lane = t & 31;
    const int gid = lane >> 2, tid4 = lane & 3;
    const int row0 = blockIdx.x * 128;

    // stage full B once: Bs[f][col] = Md[r=col>>2][f][h=col&3]
    #pragma unroll
    for (int i = 0; i < 8; i++) {
        int idx = t + i * 256;           // 2048
        int f = idx >> 4, col = idx & 15;
        float v = 0.f;
        if (col < RR * HH) {
            int r = col >> 2, h = col & 3;
            v = g_Md[r * HIDF * HH + f * HH + h];
        }
        Bs[f * 16 + col] = f2tf(v);
    }

    float acc[2][4];
    #pragma unroll
    for (int nt = 0; nt < 2; nt++)
        #pragma unroll
        for (int q = 0; q < 4; q++) acc[nt][q] = 0.f;

    for (int k0 = 0; k0 < HIDF; k0 += 32) {
        #pragma unroll
        for (int i = 0; i < 4; i++) {
            int idx = t + i * 256;
            int row = idx >> 3, kp = (idx & 7) * 4;
            float4 v = {0.f, 0.f, 0.f, 0.f};
            if (row0 + row < NN)
                v = *(const float4*)&dst_feat[(size_t)(row0 + row) * HIDF + k0 + kp];
            unsigned* p = &As[row * 36 + kp];
            p[0] = f2tf(v.x); p[1] = f2tf(v.y); p[2] = f2tf(v.z); p[3] = f2tf(v.w);
        }
        __syncthreads();
        #pragma unroll
        for (int ks = 0; ks < 4; ks++) {
            int row = warp * 16 + gid;
            unsigned a0 = As[row * 36 + ks * 8 + tid4];
            unsigned a1 = As[(row + 8) * 36 + ks * 8 + tid4];
            unsigned a2 = As[row * 36 + ks * 8 + tid4 + 4];
            unsigned a3 = As[(row + 8) * 36 + ks * 8 + tid4 + 4];
            #pragma unroll
            for (int nt = 0; nt < 2; nt++) {
                int col = nt * 8 + gid;
                unsigned b0 = Bs[(k0 + ks * 8 + tid4) * 16 + col];
                unsigned b1 = Bs[(k0 + ks * 8 + tid4 + 4) * 16 + col];
                mma_tf32(acc[nt], a0, a1, a2, a3, b0, b1);
            }
        }
        __syncthreads();
    }

    // epilogue: scatter to g_er[(r*NN+n)*4+h], col = r*4+h
    int rowA = row0 + warp * 16 + gid;
    int rowB = rowA + 8;
    #pragma unroll
    for (int nt = 0; nt < 2; nt++) {
        #pragma unroll
        for (int cc = 0; cc < 2; cc++) {
            int col = nt * 8 + tid4 * 2 + cc;
            if (col < RR * HH) {
                int r = col >> 2, h = col & 3;
                float bd = g_bd[col];
                if (rowA < NN)
                    g_er[((size_t)r * NN + rowA) * HH + h] = acc[nt][cc] + bd;
                if (rowB < NN)
                    g_er[((size_t)r * NN + rowB) * HH + h] = acc[nt][cc + 2] + bd;
            }
        }
    }
}

// ---------------- K4: edge scores ------------------------------------------
__global__ void k_edge1(const int* __restrict__ src_idx, const int* __restrict__ dst_idx) {
    int idx = blockIdx.x * blockDim.x + threadIdx.x;
    if (idx >= RR * EE) return;
    int rel = idx / EE;
    int s = src_idx[idx], d = dst_idx[idx];
    float4 l  = *(const float4*)&g_el[((size_t)rel * NN + s) * HH];
    float4 rv = *(const float4*)&g_er[((size_t)rel * NN + d) * HH];
    float x0 = l.x + rv.x, x1 = l.y + rv.y, x2 = l.z + rv.z, x3 = l.w + rv.w;
    x0 = x0 > 0.f ? x0 : 0.2f * x0;
    x1 = x1 > 0.f ? x1 : 0.2f * x1;
    x2 = x2 > 0.f ? x2 : 0.2f * x2;
    x3 = x3 > 0.f ? x3 : 0.2f * x3;
    float4 ex = {__expf(x0), __expf(x1), __expf(x2), __expf(x3)};
    *(float4*)&g_ex[(size_t)idx * 4] = ex;
    red_add_v4(&g_ssum[((size_t)rel * NN + d) * HH], ex);
}

// ---------------- K5: aggregation ------------------------------------------
__global__ void k_edge2(const int* __restrict__ src_idx, const int* __restrict__ dst_idx) {
    int gw = (blockIdx.x * blockDim.x + threadIdx.x) >> 5;
    if (gw >= RR * EE) return;
    int lane = threadIdx.x & 31;
    int rel = gw / EE;
    int s = src_idx[gw], d = dst_idx[gw];
    int h = lane >> 3;
    float exv = g_ex[(size_t)gw * 4 + h];
    float sv  = g_ssum[((size_t)rel * NN + d) * HH + h];
    float alpha = __fdividef(exv, sv + 1e-9f);
    float4 v = *(const float4*)&g_hs[((size_t)rel * NN + s) * HD + lane * 4];
    v.x *= alpha; v.y *= alpha; v.z *= alpha; v.w *= alpha;
    red_add_v4(&g_rst[((size_t)rel * NN + d) * HD + lane * 4], v);
}

// ---------------- K6: wsum += tanh(elu(rst+bias)@W1+b1)@W2 (no z write) -----
__global__ __launch_bounds__(256) void k_gemm_w(const float* __restrict__ bias_g,
                                                const float* __restrict__ W1,
                                                const float* __restrict__ b1,
                                                const float* __restrict__ W2) {
    __shared__ unsigned As[128 * 36];
    __shared__ unsigned Ws[32 * 136];
    const int r = blockIdx.y;
    const int row0 = blockIdx.x * 128;
    const int t = threadIdx.x;
    const int warp = t >> 5, lane = t & 31;
    const int wm = warp & 3, wn = warp >> 2;
    const int gid = lane >> 2, tid4 = lane & 3;
    const float* Z = g_rst + (size_t)r * NN * HD;

    float acc[2][8][4];
    #pragma unroll
    for (int mt = 0; mt < 2; mt++)
        #pragma unroll
        for (int nt = 0; nt < 8; nt++)
            #pragma unroll
            for (int q = 0; q < 4; q++) acc[mt][nt][q] = 0.f;

    for (int k0 = 0; k0 < HD; k0 += 32) {
        #pragma unroll
        for (int i = 0; i < 4; i++) {
            int idx = t + i * 256;
            int row = idx >> 3, kp = (idx & 7) * 4;
            float4 v = {0.f, 0.f, 0.f, 0.f};
            int grow = row0 + row;
            if (grow < NN) {
                v = *(const float4*)&Z[(size_t)grow * HD + k0 + kp];
                const float* bg = &bias_g[r * HD + k0 + kp];
                v.x = eluf(v.x + bg[0]); v.y = eluf(v.y + bg[1]);
                v.z = eluf(v.z + bg[2]); v.w = eluf(v.w + bg[3]);
            }
            unsigned* p = &As[row * 36 + kp];
            p[0] = f2tf(v.x); p[1] = f2tf(v.y); p[2] = f2tf(v.z); p[3] = f2tf(v.w);
        }
        #pragma unroll
        for (int i = 0; i < 4; i++) {
            int idx = t + i * 256;
            int kr = idx >> 5, col = (idx & 31) * 4;
            float4 v = *(const float4*)&W1[(k0 + kr) * 128 + col];
            unsigned* p = &Ws[kr * 136 + col];
            p[0] = f2tf(v.x); p[1] = f2tf(v.y); p[2] = f2tf(v.z); p[3] = f2tf(v.w);
        }
        __syncthreads();
        #pragma unroll
        for (int ks = 0; ks < 4; ks++) {
            unsigned a[2][4];
            #pragma unroll
            for (int mt = 0; mt < 2; mt++) {
                int row = wm * 32 + mt * 16 + gid;
                a[mt][0] = As[row * 36 + ks * 8 + tid4];
                a[mt][1] = As[(row + 8) * 36 + ks * 8 + tid4];
                a[mt][2] = As[row * 36 + ks * 8 + tid4 + 4];
                a[mt][3] = As[(row + 8) * 36 + ks * 8 + tid4 + 4];
            }
            #pragma unroll
            for (int nt = 0; nt < 8; nt++) {
                int col = wn * 64 + nt * 8 + gid;
                unsigned b0 = Ws[(ks * 8 + tid4) * 136 + col];
                unsigned b1 = Ws[(ks * 8 + tid4 + 4) * 136 + col];
                mma_tf32(acc[0][nt], a[0][0], a[0][1], a[0][2], a[0][3], b0, b1);
                mma_tf32(acc[1][nt], a[1][0], a[1][1], a[1][2], a[1][3], b0, b1);
            }
        }
        __syncthreads();
    }

    float2 b1v[8], w2v[8];
    #pragma unroll
    for (int nt = 0; nt < 8; nt++) {
        int col = wn * 64 + nt * 8 + tid4 * 2;
        b1v[nt] = *(const float2*)&b1[col];
        w2v[nt] = *(const float2*)&W2[col];
    }
    float wpart = 0.f;
    #pragma unroll
    for (int mt = 0; mt < 2; mt++) {
        int rbase = row0 + wm * 32 + mt * 16;
        float s0 = 0.f, s1 = 0.f;
        #pragma unroll
        for (int nt = 0; nt < 8; nt++) {
            s0 += tanh_fast(acc[mt][nt][0] + b1v[nt].x) * w2v[nt].x
                + tanh_fast(acc[mt][nt][1] + b1v[nt].y) * w2v[nt].y;
            s1 += tanh_fast(acc[mt][nt][2] + b1v[nt].x) * w2v[nt].x
                + tanh_fast(acc[mt][nt][3] + b1v[nt].y) * w2v[nt].y;
        }
        s0 += __shfl_xor_sync(0xffffffffu, s0, 1);
        s0 += __shfl_xor_sync(0xffffffffu, s0, 2);
        s1 += __shfl_xor_sync(0xffffffffu, s1, 1);
        s1 += __shfl_xor_sync(0xffffffffu, s1, 2);
        if (tid4 == 0) {
            if (rbase + gid < NN)     wpart += s0;
            if (rbase + gid + 8 < NN) wpart += s1;
        }
    }
    wpart += __shfl_xor_sync(0xffffffffu, wpart, 4);
    wpart += __shfl_xor_sync(0xffffffffu, wpart, 8);
    wpart += __shfl_xor_sync(0xffffffffu, wpart, 16);
    if (lane == 0) atomicAdd(&g_wsum[r], wpart);
}

// ---------------- K7: semantic softmax -------------------------------------
__global__ void k_softmax(float* __restrict__ out) {
    if (threadIdx.x == 0 && blockIdx.x == 0) {
        float w0 = g_wsum[0] / (float)NN;
        float w1 = g_wsum[1] / (float)NN;
        float w2 = g_wsum[2] / (float)NN;
        float m = fmaxf(w0, fmaxf(w1, w2));
        float e0 = expf(w0 - m), e1 = expf(w1 - m), e2 = expf(w2 - m);
        float s = e0 + e1 + e2;
        g_a[0] = e0 / s;  g_a[1] = e1 / s;  g_a[2] = e2 / s;
        out[(size_t)NN * HD + 0] = g_a[0];
        out[(size_t)NN * HD + 1] = g_a[1];
        out[(size_t)NN * HD + 2] = g_a[2];
    }
}

// ---------------- K8: z = sum_r a[r] * elu(rst_r + bias_r) -------------------
__global__ void k_combine(const float* __restrict__ bias_g, float* __restrict__ out) {
    size_t i = blockIdx.x * (size_t)blockDim.x + threadIdx.x;
    size_t n4 = (size_t)NN * HD / 4;
    if (i >= n4) return;
    int c = ((int)(i & 31)) * 4;
    float a0 = g_a[0], a1 = g_a[1], a2 = g_a[2];
    float4 bg0 = *(const float4*)&bias_g[0 * HD + c];
    float4 bg1 = *(const float4*)&bias_g[1 * HD + c];
    float4 bg2 = *(const float4*)&bias_g[2 * HD + c];
    const float4* z0 = (const float4*)g_rst;
    const float4* z1 = z0 + n4;
    const float4* z2 = z1 + n4;
    float4 x = z0[i], y = z1[i], z = z2[i];
    float4 o;
    o.x = a0 * eluf(x.x + bg0.x) + a1 * eluf(y.x + bg1.x) + a2 * eluf(z.x + bg2.x);
    o.y = a0 * eluf(x.y + bg0.y) + a1 * eluf(y.y + bg1.y) + a2 * eluf(z.y + bg2.y);
    o.z = a0 * eluf(x.z + bg0.z) + a1 * eluf(y.z + bg1.z) + a2 * eluf(z.z + bg2.z);
    o.w = a0 * eluf(x.w + bg0.w) + a1 * eluf(y.w + bg1.w) + a2 * eluf(z.w + bg2.w);
    ((float4*)out)[i] = o;
}

// ---------------- launcher --------------------------------------------------
extern "C" void kernel_launch(void* const* d_in, const int* in_sizes, int n_in,
                              void* d_out, int out_size) {
    const float* dst_feat  = (const float*)d_in[0];
    const float* src_feats = (const float*)d_in[1];
    const int*   src_idx   = (const int*)  d_in[2];
    const int*   dst_idx   = (const int*)  d_in[3];
    const float* Wt_dst    = (const float*)d_in[4];
    const float* bt_dst    = (const float*)d_in[5];
    const float* Wt_src    = (const float*)d_in[6];
    const float* bt_src    = (const float*)d_in[7];
    const float* Wg        = (const float*)d_in[8];
    const float* attn_l    = (const float*)d_in[9];
    const float* attn_r    = (const float*)d_in[10];
    const float* bias_g    = (const float*)d_in[11];
    const float* W1        = (const float*)d_in[12];
    const float* b1        = (const float*)d_in[13];
    const float* W2        = (const float*)d_in[14];
    float* out = (float*)d_out;

    k_prep<<<RR * 9, 256>>>(Wt_dst, bt_dst, Wt_src, bt_src, Wg, attn_r);
    k_fill<<<4096, 256>>>();
    k_gemm_hs<<<dim3((NN + 127) / 128, RR), 256>>>(src_feats, attn_l);
    k_er<<<(NN + 127) / 128, 256>>>(dst_feat);
    k_edge1<<<(RR * EE + 255) / 256, 256>>>(src_idx, dst_idx);
    k_edge2<<<(RR * EE * 32) / 256, 256>>>(src_idx, dst_idx);
    k_gemm_w<<<dim3((NN + 127) / 128, RR), 256>>>(bias_g, W1, b1, W2);
    k_softmax<<<1, 32>>>(out);
    k_combine<<<(NN * HD / 4 + 255) / 256, 256>>>(bias_g, out);
}

// round 7
// speedup vs baseline: 1.7901x; 1.0385x over previous
#include <cuda_runtime.h>
#include <math.h>

#define NN   100000
#define RR   3
#define EE   320000
#define HIDF 128
#define HH   4
#define DDIM 32
#define HD   128

// ---------------- scratch (device globals; 16B aligned for v4 ops) ---------
__device__ __align__(16) float g_hs  [RR * NN * HD];
__device__ __align__(16) float g_rst [RR * NN * HD];   // unnormalized Σ ex*hs
__device__ __align__(16) float g_el  [RR * NN * HH];
__device__ __align__(16) float g_er  [RR * NN * HH];
__device__ __align__(16) float g_ssum[RR * NN * HH];
__device__ __align__(16) float g_Wcomb[RR * HIDF * HD];
__device__ __align__(16) float g_bcomb[RR * HD];
__device__ __align__(16) float g_Md  [RR * HIDF * HH];
__device__ __align__(16) float g_bd  [RR * HH];
__device__ __align__(16) float g_wsum[RR];
__device__ __align__(16) float g_a   [RR];

// ---------------- helpers --------------------------------------------------
__device__ __forceinline__ void red_add_v4(float* p, float4 v) {
    asm volatile("red.global.add.v4.f32 [%0], {%1,%2,%3,%4};"
                 :: "l"(p), "f"(v.x), "f"(v.y), "f"(v.z), "f"(v.w) : "memory");
}
__device__ __forceinline__ void red_add_f32(float* p, float v) {
    asm volatile("red.global.add.f32 [%0], %1;" :: "l"(p), "f"(v) : "memory");
}
__device__ __forceinline__ float tanh_fast(float x) {
    float y; asm("tanh.approx.f32 %0, %1;" : "=f"(y) : "f"(x)); return y;
}
__device__ __forceinline__ float eluf(float x) {
    return x > 0.f ? x : expm1f(x);
}
__device__ __forceinline__ unsigned f2tf(float x) {
    unsigned y; asm("cvt.rna.tf32.f32 %0, %1;" : "=r"(y) : "f"(x)); return y;
}
__device__ __forceinline__ void mma_tf32(float c[4], unsigned a0, unsigned a1,
                                         unsigned a2, unsigned a3,
                                         unsigned b0, unsigned b1) {
    asm volatile(
        "mma.sync.aligned.m16n8k8.row.col.f32.tf32.tf32.f32 "
        "{%0,%1,%2,%3}, {%4,%5,%6,%7}, {%8,%9}, {%0,%1,%2,%3};"
        : "+f"(c[0]), "+f"(c[1]), "+f"(c[2]), "+f"(c[3])
        : "r"(a0), "r"(a1), "r"(a2), "r"(a3), "r"(b0), "r"(b1));
}

// ---------------- K1: zero accumulators ------------------------------------
__global__ void k_fill() {
    size_t i = blockIdx.x * (size_t)blockDim.x + threadIdx.x;
    size_t stride = gridDim.x * (size_t)blockDim.x;
    float4 z4 = {0.f, 0.f, 0.f, 0.f};
    size_t n4 = ((size_t)RR * NN * HD) / 4;
    for (size_t k = i; k < n4; k += stride) ((float4*)g_rst)[k] = z4;
    size_t m4 = ((size_t)RR * NN * HH) / 4;
    for (size_t k = i; k < m4; k += stride) ((float4*)g_ssum)[k] = z4;
    if (i < RR) g_wsum[i] = 0.f;
}

// ---------------- K0: combined weights -------------------------------------
__global__ void k_prep(const float* __restrict__ Wt_dst, const float* __restrict__ bt_dst,
                       const float* __restrict__ Wt_src, const float* __restrict__ bt_src,
                       const float* __restrict__ Wg,     const float* __restrict__ attn_r) {
    int r = blockIdx.x / 9;
    int part = blockIdx.x % 9;
    int t = threadIdx.x; // 256
    const float* wg = Wg + r * HIDF * HD;
    if (part < 8) {
        const float* wts = Wt_src + r * HIDF * HIDF;
        #pragma unroll 1
        for (int it = 0; it < 8; it++) {
            int idx = part * 2048 + it * 256 + t;
            int f = idx >> 7, j = idx & 127;
            float s = 0.f;
            for (int g = 0; g < HIDF; g++)
                s += wts[f * HIDF + g] * wg[g * HD + j];
            g_Wcomb[r * HIDF * HD + idx] = s;
        }
    } else {
        __shared__ float ur[HIDF * HH];
        const float* ar = attn_r + r * HH * DDIM;
        for (int i = t; i < HIDF * HH; i += 256) {
            int f = i >> 2, h = i & 3;
            float s = 0.f;
            for (int d = 0; d < DDIM; d++)
                s += wg[f * HD + h * DDIM + d] * ar[h * DDIM + d];
            ur[i] = s;
        }
        __syncthreads();
        for (int i = t; i < HIDF * HH; i += 256) {
            int f = i >> 2, h = i & 3;
            float s = 0.f;
            for (int g = 0; g < HIDF; g++)
                s += Wt_dst[f * HIDF + g] * ur[g * HH + h];
            g_Md[r * HIDF * HH + i] = s;
        }
        if (t < HH) {
            float s = 0.f;
            for (int g = 0; g < HIDF; g++) s += bt_dst[g] * ur[g * HH + t];
            g_bd[r * HH + t] = s;
        }
        if (t < HD) {
            const float* bts = bt_src + r * HIDF;
            float s = 0.f;
            for (int f = 0; f < HIDF; f++) s += bts[f] * wg[f * HD + t];
            g_bcomb[r * HD + t] = s;
        }
    }
}

// ---------------- K3: er = dst_feat @ Mdall + bd  (tf32 MMA, N=16 padded) ---
__global__ __launch_bounds__(256) void k_er(const float* __restrict__ dst_feat) {
    __shared__ unsigned As[128 * 36];
    __shared__ unsigned Bs[128 * 16];
    const int t = threadIdx.x;
    const int warp = t >> 5, lane = t & 31;
    const int gid = lane >> 2, tid4 = lane & 3;
    const int row0 = blockIdx.x * 128;

    #pragma unroll
    for (int i = 0; i < 8; i++) {
        int idx = t + i * 256;
        int f = idx >> 4, col = idx & 15;
        float v = 0.f;
        if (col < RR * HH) {
            int r = col >> 2, h = col & 3;
            v = g_Md[r * HIDF * HH + f * HH + h];
        }
        Bs[f * 16 + col] = f2tf(v);
    }

    float acc[2][4];
    #pragma unroll
    for (int nt = 0; nt < 2; nt++)
        #pragma unroll
        for (int q = 0; q < 4; q++) acc[nt][q] = 0.f;

    for (int k0 = 0; k0 < HIDF; k0 += 32) {
        #pragma unroll
        for (int i = 0; i < 4; i++) {
            int idx = t + i * 256;
            int row = idx >> 3, kp = (idx & 7) * 4;
            float4 v = {0.f, 0.f, 0.f, 0.f};
            if (row0 + row < NN)
                v = *(const float4*)&dst_feat[(size_t)(row0 + row) * HIDF + k0 + kp];
            unsigned* p = &As[row * 36 + kp];
            p[0] = f2tf(v.x); p[1] = f2tf(v.y); p[2] = f2tf(v.z); p[3] = f2tf(v.w);
        }
        __syncthreads();
        #pragma unroll
        for (int ks = 0; ks < 4; ks++) {
            int row = warp * 16 + gid;
            unsigned a0 = As[row * 36 + ks * 8 + tid4];
            unsigned a1 = As[(row + 8) * 36 + ks * 8 + tid4];
            unsigned a2 = As[row * 36 + ks * 8 + tid4 + 4];
            unsigned a3 = As[(row + 8) * 36 + ks * 8 + tid4 + 4];
            #pragma unroll
            for (int nt = 0; nt < 2; nt++) {
                int col = nt * 8 + gid;
                unsigned b0 = Bs[(k0 + ks * 8 + tid4) * 16 + col];
                unsigned b1 = Bs[(k0 + ks * 8 + tid4 + 4) * 16 + col];
                mma_tf32(acc[nt], a0, a1, a2, a3, b0, b1);
            }
        }
        __syncthreads();
    }

    int rowA = row0 + warp * 16 + gid;
    int rowB = rowA + 8;
    #pragma unroll
    for (int nt = 0; nt < 2; nt++) {
        #pragma unroll
        for (int cc = 0; cc < 2; cc++) {
            int col = nt * 8 + tid4 * 2 + cc;
            if (col < RR * HH) {
                int r = col >> 2, h = col & 3;
                float bd = g_bd[col];
                if (rowA < NN)
                    g_er[((size_t)r * NN + rowA) * HH + h] = acc[nt][cc] + bd;
                if (rowB < NN)
                    g_er[((size_t)r * NN + rowB) * HH + h] = acc[nt][cc + 2] + bd;
            }
        }
    }
}

// ---------------- K2: hs = src @ Wcomb + bcomb (tf32 MMA) ; el epilogue -----
__global__ __launch_bounds__(256) void k_gemm_hs(const float* __restrict__ src_feats,
                                                 const float* __restrict__ attn_l) {
    __shared__ unsigned As[128 * 36];
    __shared__ unsigned Ws[32 * 136];
    const int r = blockIdx.y;
    const int row0 = blockIdx.x * 128;
    const int t = threadIdx.x;
    const int warp = t >> 5, lane = t & 31;
    const int wm = warp & 3, wn = warp >> 2;
    const int gid = lane >> 2, tid4 = lane & 3;
    const float* A = src_feats + (size_t)r * NN * HIDF;
    const float* W = g_Wcomb + r * HIDF * HD;

    float acc[2][8][4];
    #pragma unroll
    for (int mt = 0; mt < 2; mt++)
        #pragma unroll
        for (int nt = 0; nt < 8; nt++)
            #pragma unroll
            for (int q = 0; q < 4; q++) acc[mt][nt][q] = 0.f;

    for (int k0 = 0; k0 < HIDF; k0 += 32) {
        #pragma unroll
        for (int i = 0; i < 4; i++) {
            int idx = t + i * 256;
            int row = idx >> 3, kp = (idx & 7) * 4;
            float4 v = {0.f, 0.f, 0.f, 0.f};
            if (row0 + row < NN)
                v = *(const float4*)&A[(size_t)(row0 + row) * HIDF + k0 + kp];
            unsigned* p = &As[row * 36 + kp];
            p[0] = f2tf(v.x); p[1] = f2tf(v.y); p[2] = f2tf(v.z); p[3] = f2tf(v.w);
        }
        #pragma unroll
        for (int i = 0; i < 4; i++) {
            int idx = t + i * 256;
            int kr = idx >> 5, col = (idx & 31) * 4;
            float4 v = *(const float4*)&W[(k0 + kr) * HD + col];
            unsigned* p = &Ws[kr * 136 + col];
            p[0] = f2tf(v.x); p[1] = f2tf(v.y); p[2] = f2tf(v.z); p[3] = f2tf(v.w);
        }
        __syncthreads();
        #pragma unroll
        for (int ks = 0; ks < 4; ks++) {
            unsigned a[2][4];
            #pragma unroll
            for (int mt = 0; mt < 2; mt++) {
                int row = wm * 32 + mt * 16 + gid;
                a[mt][0] = As[row * 36 + ks * 8 + tid4];
                a[mt][1] = As[(row + 8) * 36 + ks * 8 + tid4];
                a[mt][2] = As[row * 36 + ks * 8 + tid4 + 4];
                a[mt][3] = As[(row + 8) * 36 + ks * 8 + tid4 + 4];
            }
            #pragma unroll
            for (int nt = 0; nt < 8; nt++) {
                int col = wn * 64 + nt * 8 + gid;
                unsigned b0 = Ws[(ks * 8 + tid4) * 136 + col];
                unsigned b1 = Ws[(ks * 8 + tid4 + 4) * 136 + col];
                mma_tf32(acc[0][nt], a[0][0], a[0][1], a[0][2], a[0][3], b0, b1);
                mma_tf32(acc[1][nt], a[1][0], a[1][1], a[1][2], a[1][3], b0, b1);
            }
        }
        __syncthreads();
    }

    float2 alv[8], bcv[8];
    #pragma unroll
    for (int nt = 0; nt < 8; nt++) {
        int col = wn * 64 + nt * 8 + tid4 * 2;
        alv[nt] = *(const float2*)&attn_l[r * HD + col];
        bcv[nt] = *(const float2*)&g_bcomb[r * HD + col];
    }
    #pragma unroll
    for (int mt = 0; mt < 2; mt++) {
        int rbase = row0 + wm * 32 + mt * 16;
        int rowA = rbase + gid, rowB = rbase + gid + 8;
        float p0[2] = {0.f, 0.f}, p1[2] = {0.f, 0.f};
        #pragma unroll
        for (int nt = 0; nt < 8; nt++) {
            int half = nt >> 2;
            float v0 = acc[mt][nt][0] + bcv[nt].x;
            float v1 = acc[mt][nt][1] + bcv[nt].y;
            float v2 = acc[mt][nt][2] + bcv[nt].x;
            float v3 = acc[mt][nt][3] + bcv[nt].y;
            p0[half] += v0 * alv[nt].x + v1 * alv[nt].y;
            p1[half] += v2 * alv[nt].x + v3 * alv[nt].y;
            int col = wn * 64 + nt * 8 + tid4 * 2;
            if (rowA < NN)
                *(float2*)&g_hs[((size_t)r * NN + rowA) * HD + col] = make_float2(v0, v1);
            if (rowB < NN)
                *(float2*)&g_hs[((size_t)r * NN + rowB) * HD + col] = make_float2(v2, v3);
        }
        #pragma unroll
        for (int hh = 0; hh < 2; hh++) {
            p0[hh] += __shfl_xor_sync(0xffffffffu, p0[hh], 1);
            p0[hh] += __shfl_xor_sync(0xffffffffu, p0[hh], 2);
            p1[hh] += __shfl_xor_sync(0xffffffffu, p1[hh], 1);
            p1[hh] += __shfl_xor_sync(0xffffffffu, p1[hh], 2);
        }
        if (tid4 == 0) {
            if (rowA < NN) {
                g_el[((size_t)r * NN + rowA) * HH + wn * 2 + 0] = p0[0];
                g_el[((size_t)r * NN + rowA) * HH + wn * 2 + 1] = p0[1];
            }
            if (rowB < NN) {
                g_el[((size_t)r * NN + rowB) * HH + wn * 2 + 0] = p1[0];
                g_el[((size_t)r * NN + rowB) * HH + wn * 2 + 1] = p1[1];
            }
        }
    }
}

// ---------------- K4: fused edge pass --------------------------------------
// rst[d] += exp(leaky(el[s]+er[d])) * hs[s];  ssum[d] += ex.  Warp per edge.
__global__ void k_edge(const int* __restrict__ src_idx, const int* __restrict__ dst_idx) {
    int gw = (blockIdx.x * blockDim.x + threadIdx.x) >> 5;
    if (gw >= RR * EE) return;
    int lane = threadIdx.x & 31;
    int rel = gw / EE;
    int s = src_idx[gw], d = dst_idx[gw];
    int h = lane >> 3;
    float elv = __ldg(&g_el[((size_t)rel * NN + s) * HH + h]);
    float erv = __ldg(&g_er[((size_t)rel * NN + d) * HH + h]);
    float x = elv + erv;
    x = x > 0.f ? x : 0.2f * x;
    float ex = __expf(x);
    float4 v = *(const float4*)&g_hs[((size_t)rel * NN + s) * HD + lane * 4];
    v.x *= ex; v.y *= ex; v.z *= ex; v.w *= ex;
    red_add_v4(&g_rst[((size_t)rel * NN + d) * HD + lane * 4], v);
    if ((lane & 7) == 0)
        red_add_f32(&g_ssum[((size_t)rel * NN + d) * HH + h], ex);
}

// ---------------- K6: wsum += tanh(elu(rst/ssum+bias)@W1+b1)@W2 -------------
__global__ __launch_bounds__(256) void k_gemm_w(const float* __restrict__ bias_g,
                                                const float* __restrict__ W1,
                                                const float* __restrict__ b1,
                                                const float* __restrict__ W2) {
    __shared__ unsigned As[128 * 36];
    __shared__ unsigned Ws[32 * 136];
    const int r = blockIdx.y;
    const int row0 = blockIdx.x * 128;
    const int t = threadIdx.x;
    const int warp = t >> 5, lane = t & 31;
    const int wm = warp & 3, wn = warp >> 2;
    const int gid = lane >> 2, tid4 = lane & 3;
    const float* Z = g_rst + (size_t)r * NN * HD;

    float acc[2][8][4];
    #pragma unroll
    for (int mt = 0; mt < 2; mt++)
        #pragma unroll
        for (int nt = 0; nt < 8; nt++)
            #pragma unroll
            for (int q = 0; q < 4; q++) acc[mt][nt][q] = 0.f;

    for (int k0 = 0; k0 < HD; k0 += 32) {
        #pragma unroll
        for (int i = 0; i < 4; i++) {
            int idx = t + i * 256;
            int row = idx >> 3, kp = (idx & 7) * 4;
            float4 v = {0.f, 0.f, 0.f, 0.f};
            int grow = row0 + row;
            if (grow < NN) {
                int h = (k0 + kp) >> 5;
                float sv = g_ssum[((size_t)r * NN + grow) * HH + h];
                float inv = __fdividef(1.f, sv + 1e-9f);
                v = *(const float4*)&Z[(size_t)grow * HD + k0 + kp];
                const float* bg = &bias_g[r * HD + k0 + kp];
                v.x = eluf(v.x * inv + bg[0]); v.y = eluf(v.y * inv + bg[1]);
                v.z = eluf(v.z * inv + bg[2]); v.w = eluf(v.w * inv + bg[3]);
            }
            unsigned* p = &As[row * 36 + kp];
            p[0] = f2tf(v.x); p[1] = f2tf(v.y); p[2] = f2tf(v.z); p[3] = f2tf(v.w);
        }
        #pragma unroll
        for (int i = 0; i < 4; i++) {
            int idx = t + i * 256;
            int kr = idx >> 5, col = (idx & 31) * 4;
            float4 v = *(const float4*)&W1[(k0 + kr) * 128 + col];
            unsigned* p = &Ws[kr * 136 + col];
            p[0] = f2tf(v.x); p[1] = f2tf(v.y); p[2] = f2tf(v.z); p[3] = f2tf(v.w);
        }
        __syncthreads();
        #pragma unroll
        for (int ks = 0; ks < 4; ks++) {
            unsigned a[2][4];
            #pragma unroll
            for (int mt = 0; mt < 2; mt++) {
                int row = wm * 32 + mt * 16 + gid;
                a[mt][0] = As[row * 36 + ks * 8 + tid4];
                a[mt][1] = As[(row + 8) * 36 + ks * 8 + tid4];
                a[mt][2] = As[row * 36 + ks * 8 + tid4 + 4];
                a[mt][3] = As[(row + 8) * 36 + ks * 8 + tid4 + 4];
            }
            #pragma unroll
            for (int nt = 0; nt < 8; nt++) {
                int col = wn * 64 + nt * 8 + gid;
                unsigned b0 = Ws[(ks * 8 + tid4) * 136 + col];
                unsigned b1 = Ws[(ks * 8 + tid4 + 4) * 136 + col];
                mma_tf32(acc[0][nt], a[0][0], a[0][1], a[0][2], a[0][3], b0, b1);
                mma_tf32(acc[1][nt], a[1][0], a[1][1], a[1][2], a[1][3], b0, b1);
            }
        }
        __syncthreads();
    }

    float2 b1v[8], w2v[8];
    #pragma unroll
    for (int nt = 0; nt < 8; nt++) {
        int col = wn * 64 + nt * 8 + tid4 * 2;
        b1v[nt] = *(const float2*)&b1[col];
        w2v[nt] = *(const float2*)&W2[col];
    }
    float wpart = 0.f;
    #pragma unroll
    for (int mt = 0; mt < 2; mt++) {
        int rbase = row0 + wm * 32 + mt * 16;
        float s0 = 0.f, s1 = 0.f;
        #pragma unroll
        for (int nt = 0; nt < 8; nt++) {
            s0 += tanh_fast(acc[mt][nt][0] + b1v[nt].x) * w2v[nt].x
                + tanh_fast(acc[mt][nt][1] + b1v[nt].y) * w2v[nt].y;
            s1 += tanh_fast(acc[mt][nt][2] + b1v[nt].x) * w2v[nt].x
                + tanh_fast(acc[mt][nt][3] + b1v[nt].y) * w2v[nt].y;
        }
        s0 += __shfl_xor_sync(0xffffffffu, s0, 1);
        s0 += __shfl_xor_sync(0xffffffffu, s0, 2);
        s1 += __shfl_xor_sync(0xffffffffu, s1, 1);
        s1 += __shfl_xor_sync(0xffffffffu, s1, 2);
        if (tid4 == 0) {
            if (rbase + gid < NN)     wpart += s0;
            if (rbase + gid + 8 < NN) wpart += s1;
        }
    }
    wpart += __shfl_xor_sync(0xffffffffu, wpart, 4);
    wpart += __shfl_xor_sync(0xffffffffu, wpart, 8);
    wpart += __shfl_xor_sync(0xffffffffu, wpart, 16);
    if (lane == 0) atomicAdd(&g_wsum[r], wpart);
}

// ---------------- K7: semantic softmax -------------------------------------
__global__ void k_softmax(float* __restrict__ out) {
    if (threadIdx.x == 0 && blockIdx.x == 0) {
        float w0 = g_wsum[0] / (float)NN;
        float w1 = g_wsum[1] / (float)NN;
        float w2 = g_wsum[2] / (float)NN;
        float m = fmaxf(w0, fmaxf(w1, w2));
        float e0 = expf(w0 - m), e1 = expf(w1 - m), e2 = expf(w2 - m);
        float s = e0 + e1 + e2;
        g_a[0] = e0 / s;  g_a[1] = e1 / s;  g_a[2] = e2 / s;
        out[(size_t)NN * HD + 0] = g_a[0];
        out[(size_t)NN * HD + 1] = g_a[1];
        out[(size_t)NN * HD + 2] = g_a[2];
    }
}

// ---------------- K8: z = sum_r a[r] * elu(rst_r/ssum_r + bias_r) -----------
__global__ void k_combine(const float* __restrict__ bias_g, float* __restrict__ out) {
    size_t i = blockIdx.x * (size_t)blockDim.x + threadIdx.x;
    size_t n4 = (size_t)NN * HD / 4;
    if (i >= n4) return;
    int n = (int)(i >> 5);
    int c = ((int)(i & 31)) * 4;
    int h = c >> 5;
    float a0 = g_a[0], a1 = g_a[1], a2 = g_a[2];
    float i0 = __fdividef(1.f, g_ssum[((size_t)0 * NN + n) * HH + h] + 1e-9f);
    float i1 = __fdividef(1.f, g_ssum[((size_t)1 * NN + n) * HH + h] + 1e-9f);
    float i2 = __fdividef(1.f, g_ssum[((size_t)2 * NN + n) * HH + h] + 1e-9f);
    float4 bg0 = *(const float4*)&bias_g[0 * HD + c];
    float4 bg1 = *(const float4*)&bias_g[1 * HD + c];
    float4 bg2 = *(const float4*)&bias_g[2 * HD + c];
    const float4* z0 = (const float4*)g_rst;
    const float4* z1 = z0 + n4;
    const float4* z2 = z1 + n4;
    float4 x = z0[i], y = z1[i], z = z2[i];
    float4 o;
    o.x = a0 * eluf(x.x * i0 + bg0.x) + a1 * eluf(y.x * i1 + bg1.x) + a2 * eluf(z.x * i2 + bg2.x);
    o.y = a0 * eluf(x.y * i0 + bg0.y) + a1 * eluf(y.y * i1 + bg1.y) + a2 * eluf(z.y * i2 + bg2.y);
    o.z = a0 * eluf(x.z * i0 + bg0.z) + a1 * eluf(y.z * i1 + bg1.z) + a2 * eluf(z.z * i2 + bg2.z);
    o.w = a0 * eluf(x.w * i0 + bg0.w) + a1 * eluf(y.w * i1 + bg1.w) + a2 * eluf(z.w * i2 + bg2.w);
    ((float4*)out)[i] = o;
}

// ---------------- launcher --------------------------------------------------
extern "C" void kernel_launch(void* const* d_in, const int* in_sizes, int n_in,
                              void* d_out, int out_size) {
    const float* dst_feat  = (const float*)d_in[0];
    const float* src_feats = (const float*)d_in[1];
    const int*   src_idx   = (const int*)  d_in[2];
    const int*   dst_idx   = (const int*)  d_in[3];
    const float* Wt_dst    = (const float*)d_in[4];
    const float* bt_dst    = (const float*)d_in[5];
    const float* Wt_src    = (const float*)d_in[6];
    const float* bt_src    = (const float*)d_in[7];
    const float* Wg        = (const float*)d_in[8];
    const float* attn_l    = (const float*)d_in[9];
    const float* attn_r    = (const float*)d_in[10];
    const float* bias_g    = (const float*)d_in[11];
    const float* W1        = (const float*)d_in[12];
    const float* b1        = (const float*)d_in[13];
    const float* W2        = (const float*)d_in[14];
    float* out = (float*)d_out;

    // Order matters for ncu (-s window lands on the 4th launch): gemm_hs there.
    k_fill<<<4096, 256>>>();
    k_prep<<<RR * 9, 256>>>(Wt_dst, bt_dst, Wt_src, bt_src, Wg, attn_r);
    k_er<<<(NN + 127) / 128, 256>>>(dst_feat);
    k_gemm_hs<<<dim3((NN + 127) / 128, RR), 256>>>(src_feats, attn_l);
    k_edge<<<(RR * EE * 32) / 256, 256>>>(src_idx, dst_idx);
    k_gemm_w<<<dim3((NN + 127) / 128, RR), 256>>>(bias_g, W1, b1, W2);
    k_softmax<<<1, 32>>>(out);
    k_combine<<<(NN * HD / 4 + 255) / 256, 256>>>(bias_g, out);
}